// round 14
// baseline (speedup 1.0000x reference)
#include <cuda_runtime.h>

#define TB 1024
#define NB 4
#define GRID 148
#define NTHR 512

typedef unsigned long long u64;

// ---------------- global scratch ----------------
#define CM_OFF 0          // cross K-moments (45 alphas x 12): 4*8*540 = 17280
#define CN_OFF 17280      // cross Q-moments: 4*8*45 = 1440
#define MOM_TOTAL 18720
__device__ float  g_mom[MOM_TOTAL];
__device__ float  g_bmp[128][60];          // blk partial moments (raw)
__device__ float4 g_bq4[NB][TB][16];       // blk q, [b][t][blk]
__device__ float  g_ab[NB][TB][64];
__device__ float  g_cq[NB][8][TB][8];
__device__ float  g_ck[NB][8][TB][8];
__device__ float  g_ao[NB][TB][64];

__device__ unsigned g_bar_cnt = 0;
__device__ unsigned g_bar_gen = 0;

__device__ __forceinline__ void grid_sync() {
    __syncthreads();
    if (threadIdx.x == 0) {
        unsigned gen;
        asm volatile("ld.global.acquire.gpu.u32 %0, [%1];" : "=r"(gen) : "l"(&g_bar_gen));
        __threadfence();
        unsigned prev;
        asm volatile("atom.global.release.gpu.add.u32 %0, [%1], %2;"
                     : "=r"(prev) : "l"(&g_bar_cnt), "r"(1u) : "memory");
        if (prev == GRID - 1) {
            asm volatile("st.global.relaxed.gpu.u32 [%0], %1;" :: "l"(&g_bar_cnt), "r"(0u) : "memory");
            asm volatile("st.global.release.gpu.u32 [%0], %1;" :: "l"(&g_bar_gen), "r"(gen + 1u) : "memory");
        } else {
            unsigned cur;
            do {
                asm volatile("ld.global.acquire.gpu.u32 %0, [%1];" : "=r"(cur) : "l"(&g_bar_gen));
            } while (cur == gen);
        }
    }
    __syncthreads();
}

#define GBAR(id, cnt) asm volatile("bar.sync %0, %1;" :: "r"(id), "r"(cnt) : "memory")

__device__ __forceinline__ u64 fma2_(u64 a, u64 b, u64 c) {
    u64 r; asm("fma.rn.f32x2 %0, %1, %2, %3;" : "=l"(r) : "l"(a), "l"(b), "l"(c)); return r;
}
__device__ __forceinline__ u64 mul2_(u64 a, u64 b) {
    u64 r; asm("mul.rn.f32x2 %0, %1, %2;" : "=l"(r) : "l"(a), "l"(b)); return r;
}
__device__ __forceinline__ u64 add2_(u64 a, u64 b) {
    u64 r; asm("add.rn.f32x2 %0, %1, %2;" : "=l"(r) : "l"(a), "l"(b)); return r;
}
__device__ __forceinline__ float2 unpk_(u64 v) {
    float2 r; asm("mov.b64 {%0, %1}, %2;" : "=f"(r.x), "=f"(r.y) : "l"(v)); return r;
}
__device__ __forceinline__ u64 pk_(float lo, float hi) {
    u64 r; asm("mov.b64 %0, {%1, %2};" : "=l"(r) : "f"(lo), "f"(hi)); return r;
}
__device__ __forceinline__ float wsum(float v) {
    #pragma unroll
    for (int o = 16; o > 0; o >>= 1) v += __shfl_xor_sync(0xffffffffu, v, o);
    return v;
}
__device__ __forceinline__ float gelu_(float x) {
    return 0.5f * x * (1.0f + erff(x * 0.7071067811865476f));
}
__device__ __forceinline__ void cross_alpha2(int alpha, int& deg, int& i0, int& j0, float& coef) {
    deg = 0; i0 = 0; j0 = 0; coef = 1.f;
    if (alpha == 0) { deg = 0; }
    else if (alpha < 9) { deg = 1; i0 = alpha - 1; }
    else {
        deg = 2; int r = alpha - 9; int ii = 0;
        while (r >= 8 - ii) { r -= 8 - ii; ii++; }
        i0 = ii; j0 = ii + r;
        coef = (i0 == j0) ? 0.5f : 1.f;
    }
}

// smem (floats): [0,36864) epi weights | [36864,37520) small | [37520,37880) sN | [37880,+16704) phase scratch
#define PS_OFF 37880
#define SCRATCH_FLOATS 16704
#define SMEM_FLOATS (PS_OFF + SCRATCH_FLOATS)
#define SMEM_BYTES (SMEM_FLOATS * 4)

#define KPS 522   // phase A key/value row stride (522 % 32 == 10 -> 8 distinct banks)

__global__ void __launch_bounds__(NTHR, 1)
k_all(const float* __restrict__ M,
      const int* __restrict__ tok,
      const float* __restrict__ Wqkv_blk, const float* __restrict__ bqkv_blk,
      const float* __restrict__ Wo_blk,   const float* __restrict__ bo_blk,
      const float* __restrict__ Wqkv_c,   const float* __restrict__ bqkv_c,
      const float* __restrict__ Woc,      const float* __restrict__ boc,
      const float* __restrict__ W1,       const float* __restrict__ b1,
      const float* __restrict__ W2,       const float* __restrict__ b2,
      const float* __restrict__ g1,       const float* __restrict__ be1,
      const float* __restrict__ g2,       const float* __restrict__ be2,
      const float* __restrict__ semb,     const float* __restrict__ alpha,
      float* __restrict__ out)
{
    extern __shared__ float sm[];
    const int tid = threadIdx.x;
    const int bid = blockIdx.x;

    float* sWoP = sm;
    float* sW1P = sm + 4096;
    float* sW2P = sm + 20480;
    float* sSm  = sm + 36864;
    float* sboc = sSm;        float* sb1  = sSm + 64;  float* sb2  = sSm + 320;
    float* sg1  = sSm + 384;  float* sbe1 = sSm + 448; float* sg2  = sSm + 512;
    float* sbe2 = sSm + 576;  float* salp = sSm + 640;
    float* sN = sm + 37520;
    float* ps = sm + PS_OFF;

    // ---------- prologue: epilogue weights ----------
    for (int i = tid; i < 4096; i += NTHR) {
        int d = i >> 6, j = i & 63;
        sWoP[j * 64 + (d & 31) * 2 + (d >> 5)] = Woc[i];
    }
    for (int i = tid; i < 16384; i += NTHR) {
        int j = i >> 6, d = i & 63;
        sW1P[d * 256 + ((j >> 6) * 32 + (j & 31)) * 2 + ((j >> 5) & 1)] = W1[i];
    }
    for (int i = tid; i < 16384; i += NTHR) {
        int d = i >> 8, j = i & 255;
        sW2P[j * 64 + (d & 31) * 2 + (d >> 5)] = W2[i];
    }
    for (int i = tid; i < 64; i += NTHR) { sboc[i] = boc[i]; sb2[i] = b2[i];
                                           sg1[i] = g1[i]; sbe1[i] = be1[i];
                                           sg2[i] = g2[i]; sbe2[i] = be2[i]; }
    if (tid < 256) sb1[tid] = b1[tid];
    if (tid < 16) salp[tid] = alpha[tid];

    // ================= Phase A: blk QKV + partial moments. 128 CTAs =================
    if (bid < 128) {
        int b = bid >> 5, blk = (bid >> 1) & 15, half = bid & 1;
        float* sW  = ps;              // 768
        float* sB  = ps + 768;        // 192
        float* sKP = ps + 960;        // 8 rows x KPS
        float* sPart = ps + 960 + 8 * KPS;   // 540

        for (int i = tid; i < 768; i += NTHR) sW[i] = Wqkv_blk[i];
        if (tid < 192) sB[tid] = bqkv_blk[tid];
        __syncthreads();

        int rb = blk >> 2, cb = blk & 3;
        int basec = 16 * rb + 2 * cb;
        const float* W  = sW + blk * 48;
        const float* bb = sB + blk * 12;
        const float qs = 0.70710678118654752f;

        int t = half * 512 + tid;
        {
            const float* Mr = M + ((size_t)(b * 1024 + t)) * 64;
            float2 xa = *(const float2*)(Mr + basec);
            float2 xb = *(const float2*)(Mr + basec + 8);
            float x0 = xa.x, x1 = xa.y, x2 = xb.x, x3 = xb.y;
            float o[12];
            #pragma unroll
            for (int j = 0; j < 12; j++)
                o[j] = fmaf(W[j*4], x0, fmaf(W[j*4+1], x1, fmaf(W[j*4+2], x2, fmaf(W[j*4+3], x3, bb[j]))));
            g_bq4[b][t][blk] = make_float4(o[0]*qs, o[1]*qs, o[2]*qs, o[3]*qs);
            #pragma unroll
            for (int c = 0; c < 4; c++) {
                sKP[c * KPS + tid]       = o[4 + c];
                sKP[(4 + c) * KPS + tid] = o[8 + c];
            }
        }
        __syncthreads();

        // partial moments deg<=3 over 512 tokens (256 pairs): 8 subs x 60 units
        {
            int sub = tid >> 6, u = tid & 63;
            if (u < 60) {
                int h = u / 30, rem = u % 30, al = rem / 3, g = rem % 3;
                const int A_[10] = {0,1,0,2,1,0,3,2,1,0};
                const int B_[10] = {0,0,1,0,1,2,0,1,2,3};
                int a = A_[al], be = B_[al], ab = a + be;
                const float* k0base = sKP + (2*h) * KPS;
                const float* k1base = sKP + (2*h + 1) * KPS;
                const float* vbase  = (g < 2) ? (sKP + (4 + 2*h + g) * KPS) : k0base;
                const u64 ONE2 = pk_(1.f, 1.f);
                u64 acc2 = 0ull;
                int p0 = sub * 32;
                #pragma unroll 4
                for (int p = p0; p < p0 + 32; p++) {
                    u64 K0 = *(const u64*)(k0base + 2 * p);
                    u64 K1 = *(const u64*)(k1base + 2 * p);
                    u64 f0 = (0 < a) ? K0 : ((0 < ab) ? K1 : ONE2);
                    u64 f1 = (1 < a) ? K0 : ((1 < ab) ? K1 : ONE2);
                    u64 f2 = (2 < a) ? K0 : ((2 < ab) ? K1 : ONE2);
                    u64 m2 = mul2_(mul2_(f0, f1), f2);
                    if (g == 2) acc2 = add2_(acc2, m2);
                    else        acc2 = fma2_(m2, *(const u64*)(vbase + 2 * p), acc2);
                }
                float2 f = unpk_(acc2);
                sPart[u * 9 + sub] = f.x + f.y;
            }
        }
        __syncthreads();
        if (tid < 60) {
            float s = 0.f;
            #pragma unroll
            for (int k = 0; k < 8; k++) s += sPart[tid * 9 + k];
            g_bmp[bid][tid] = s;     // raw (invf applied in B)
        }
    } else {
        // 20 idle CTAs zero cross moment buffer
        for (int i = (bid - 128) * NTHR + tid; i < MOM_TOTAL; i += 20 * NTHR)
            g_mom[i] = 0.f;
    }
    grid_sync();   // bar1: g_bq4, g_bmp, zeroed cross moments

    // ================= Phase B: blk eval + cross QKV + K-moments. 128 CTAs x 32 tokens =================
    if (bid < 128) {
        float* sWq   = ps;            // 12288
        float* sBias = ps + 12288;    // 192
        float* R     = ps + 12480;    // 4224
        float* sMomB = R;             // 16 x 61 = 976 (stride 61: conflict-free)
        float4* sBQ  = (float4*)(R + 976);   // 512 float4 = 2048 floats

        for (int i = tid; i < 12288; i += NTHR) sWq[i] = Wqkv_c[i];
        if (tid < 192) sBias[tid] = bqkv_c[tid];

        int b  = bid >> 5;
        int t0 = (bid * 32) & 1023;

        // combine partial moments with invf coefs
        {
            const int A_[10] = {0,1,0,2,1,0,3,2,1,0};
            const int B_[10] = {0,0,1,0,1,2,0,1,2,3};
            const float invf[4] = {1.f, 1.f, 0.5f, 1.f/6.f};
            for (int i = tid; i < 960; i += NTHR) {
                int blkI = i / 60, u = i % 60;
                int al = (u % 30) / 3;
                float coef = invf[A_[al]] * invf[B_[al]];
                sMomB[blkI * 61 + u] =
                    (g_bmp[(b*16 + blkI)*2][u] + g_bmp[(b*16 + blkI)*2 + 1][u]) * coef;
            }
        }
        // bq for 32 tokens x 16 blks
        sBQ[tid] = g_bq4[b][t0 + (tid >> 4)][tid & 15];
        __syncthreads();

        // blk eval: thread = (token = tid>>4, blk = tid&15)
        {
            int token = tid >> 4, blk = tid & 15;
            float4 q4 = sBQ[tid];
            const float* mom = sMomB + blk * 61;
            float y[4];
            #pragma unroll
            for (int h = 0; h < 2; h++) {
                float q0 = h ? q4.z : q4.x;
                float q1 = h ? q4.w : q4.y;
                float p0[4], p1[4];
                p0[0] = 1.f; p1[0] = 1.f;
                #pragma unroll
                for (int e = 1; e < 4; e++) { p0[e] = p0[e-1] * q0; p1[e] = p1[e-1] * q1; }
                float O0 = 0.f, O1 = 0.f, Z = 0.f;
                int idx = 0;
                #pragma unroll
                for (int n = 0; n <= 3; n++) {
                    #pragma unroll
                    for (int aa = n; aa >= 0; aa--) {
                        float m = p0[aa] * p1[n - aa];
                        const float* r = mom + h * 30 + idx * 3;
                        O0 = fmaf(m, r[0], O0);
                        O1 = fmaf(m, r[1], O1);
                        Z  = fmaf(m, r[2], Z);
                        idx++;
                    }
                }
                float zi = 1.f / Z;
                y[h*2 + 0] = O0 * zi;
                y[h*2 + 1] = O1 * zi;
            }
            const float* W  = Wo_blk + blk * 16;
            const float* bb = bo_blk + blk * 4;
            float4 r;
            r.x = __ldg(&bb[0]) + __ldg(&W[0])*y[0]  + __ldg(&W[1])*y[1]  + __ldg(&W[2])*y[2]  + __ldg(&W[3])*y[3];
            r.y = __ldg(&bb[1]) + __ldg(&W[4])*y[0]  + __ldg(&W[5])*y[1]  + __ldg(&W[6])*y[2]  + __ldg(&W[7])*y[3];
            r.z = __ldg(&bb[2]) + __ldg(&W[8])*y[0]  + __ldg(&W[9])*y[1]  + __ldg(&W[10])*y[2] + __ldg(&W[11])*y[3];
            r.w = __ldg(&bb[3]) + __ldg(&W[12])*y[0] + __ldg(&W[13])*y[1] + __ldg(&W[14])*y[2] + __ldg(&W[15])*y[3];
            *(float4*)&g_ab[b][t0 + token][blk * 4] = r;
        }
        __syncthreads();

        // cross QKV (x from g_ab, written above by this CTA)
        float (*kT)[33] = (float(*)[33])R;              // 64 x 33 = 2112
        float (*vT)[33] = (float(*)[33])(R + 2112);     // 64 x 33 = 2112
        {
            int lane32 = tid & 31;
            int slice  = tid >> 5;
            int t = t0 + lane32;

            u64 x2[32];
            {
                const ulonglong2* xr = (const ulonglong2*)&g_ab[b][t][0];
                #pragma unroll
                for (int i = 0; i < 16; i++) { ulonglong2 v = xr[i]; x2[2*i] = v.x; x2[2*i+1] = v.y; }
            }
            const float qsc = 0.35355339059327373f;
            #pragma unroll
            for (int jj = 0; jj < 12; jj++) {
                int j = slice * 12 + jj;
                const ulonglong2* w4 = (const ulonglong2*)(sWq + j * 64);
                u64 a0 = 0ull, a1 = 0ull;
                #pragma unroll
                for (int d = 0; d < 16; d++) {
                    ulonglong2 w = w4[d];
                    a0 = fma2_(x2[2*d],     w.x, a0);
                    a1 = fma2_(x2[2*d + 1], w.y, a1);
                }
                float2 fa = unpk_(a0), fb = unpk_(a1);
                float val = (fa.x + fa.y) + (fb.x + fb.y) + sBias[j];
                if (j < 64) {
                    g_cq[b][j >> 3][t][j & 7] = val * qsc;
                } else if (j < 128) {
                    int c = j - 64;
                    g_ck[b][c >> 3][t][c & 7] = val;
                    kT[c][lane32] = val;
                } else {
                    vT[j - 128][lane32] = val;
                }
            }
        }
        __syncthreads();

        // fused K-moments (deg<=2), all 8 heads over this CTA's 32 keys
        if (tid < 360) {
            int h = tid / 45, al = tid % 45;
            int deg, i0, j0; float coef;
            cross_alpha2(al, deg, i0, j0, coef);
            float acc[9];
            #pragma unroll
            for (int g = 0; g < 9; g++) acc[g] = 0.f;
            #pragma unroll 4
            for (int k = 0; k < 32; k++) {
                float m = 1.f;
                if (deg >= 1) m = kT[h*8 + i0][k];
                if (deg >= 2) m *= kT[h*8 + j0][k];
                #pragma unroll
                for (int d = 0; d < 8; d++)
                    acc[d] = fmaf(m, vT[h*8 + d][k], acc[d]);
                acc[8] += m;
            }
            float* dst = &g_mom[CM_OFF + (b*8 + h)*540 + al * 12];
            #pragma unroll
            for (int g = 0; g < 9; g++) atomicAdd(dst + g, acc[g] * coef);
        }
    }
    grid_sync();   // bar2: g_ab, g_cq, g_ck, K-moments ready

    // ================= Phase C: cross eval + Q-moments. 1024 items, 8 groups x 64 =================
    if (bid < 128) {
        int g = tid >> 6, gt = tid & 63;
        float* base_ = ps + g * 836;
        float* sM = base_;                              // 540
        float (*sQT)[33] = (float(*)[33])(base_ + 540); // 8 x 33 = 264
        float* sZ = base_ + 804;                        // 32
        int item = bid * 8 + g;                         // < 1024
        int qc = item & 31, h = (item >> 5) & 7, b = item >> 8;

        for (int i = gt; i < 135; i += 64)
            ((float4*)sM)[i] = ((const float4*)&g_mom[CM_OFF + (b*8 + h)*540])[i];

        int t = qc * 32 + (gt & 31);
        float q[8];
        if (gt < 32) {
            const float4* qp = (const float4*)&g_cq[b][h][t][0];
            float4 a = qp[0], c = qp[1];
            q[0]=a.x; q[1]=a.y; q[2]=a.z; q[3]=a.w; q[4]=c.x; q[5]=c.y; q[6]=c.z; q[7]=c.w;
            #pragma unroll
            for (int i = 0; i < 8; i++) sQT[i][gt] = q[i];
        }
        GBAR(1 + g, 64);

        if (gt < 32) {
            float a0=0,a1=0,a2=0,a3=0,a4=0,a5=0,a6=0,a7=0,a8=0;
            int idx = 0;
#define FMA9(MV) { float m_ = (MV); const float4* r_ = (const float4*)(sM + idx * 12); \
    float4 ra = r_[0], rb = r_[1], rc = r_[2]; \
    a0 = fmaf(m_, ra.x, a0); a1 = fmaf(m_, ra.y, a1); a2 = fmaf(m_, ra.z, a2); a3 = fmaf(m_, ra.w, a3); \
    a4 = fmaf(m_, rb.x, a4); a5 = fmaf(m_, rb.y, a5); a6 = fmaf(m_, rb.z, a6); a7 = fmaf(m_, rb.w, a7); \
    a8 = fmaf(m_, rc.x, a8); idx++; }
            FMA9(1.f);
            #pragma unroll
            for (int i = 0; i < 8; i++) FMA9(q[i]);
            #pragma unroll
            for (int i = 0; i < 8; i++) {
                #pragma unroll
                for (int j = i; j < 8; j++) FMA9(q[i] * q[j]);
            }
#undef FMA9
            float zi = 1.f / a8;
            float4* dst = (float4*)&g_ao[b][t][h * 8];
            dst[0] = make_float4(a0*zi, a1*zi, a2*zi, a3*zi);
            dst[1] = make_float4(a4*zi, a5*zi, a6*zi, a7*zi);
            sZ[gt] = zi;
        }
        GBAR(1 + g, 64);

        if (gt < 45) {
            int deg, i0, j0; float coef;
            cross_alpha2(gt, deg, i0, j0, coef);
            float acc = 0.f;
            #pragma unroll 4
            for (int k = 0; k < 32; k++) {
                float m = sZ[k];
                if (deg >= 1) m *= sQT[i0][k];
                if (deg >= 2) m *= sQT[j0][k];
                acc += m;
            }
            atomicAdd(&g_mom[CN_OFF + (b*8 + h)*45 + gt], acc * coef);
        }
    }
    grid_sync();   // bar3: g_ao + Q-moments ready

    // ================= Phase D: epilogue + fused recv. 128 CTAs, 8 warps x 4 tokens =================
    if (bid < 128) {
        int bblk = bid >> 5;
        for (int i = tid; i < 360; i += NTHR)
            sN[i] = g_mom[CN_OFF + bblk * 360 + i];
        __syncthreads();

        int w = tid >> 5, lane = tid & 31;
        if (w < 8) {
            float* base_ = ps + w * 1792;
            int b = (bid * 32) >> 10;
            int t0 = (bid * 32 + w * 4) & 1023;

            #pragma unroll
            for (int j = 0; j < 4; j++) {
                const float* aor = &g_ao[b][t0 + j][0];
                float* s = base_ + j * 448;
                s[lane] = aor[lane]; s[lane + 32] = aor[lane + 32];
            }
            __syncwarp();

            u64 co2[4];
            #pragma unroll
            for (int j = 0; j < 4; j++) co2[j] = pk_(sboc[lane], sboc[lane + 32]);
            #pragma unroll 2
            for (int jj = 0; jj < 64; jj++) {
                u64 ww = *(const u64*)(sWoP + jj * 64 + lane * 2);
                #pragma unroll
                for (int j = 0; j < 4; j++) {
                    float aj = base_[j * 448 + jj];
                    co2[j] = fma2_(pk_(aj, aj), ww, co2[j]);
                }
            }

            float y0v[4], y1v[4];
            #pragma unroll
            for (int j = 0; j < 4; j++) {
                float2 co = unpk_(co2[j]);
                float x0 = g_ab[b][t0 + j][lane] + co.x;
                float x1 = g_ab[b][t0 + j][lane + 32] + co.y;
                float mean = wsum(x0 + x1) * (1.0f / 64.0f);
                float d0 = x0 - mean, d1 = x1 - mean;
                float var = wsum(d0 * d0 + d1 * d1) * (1.0f / 64.0f);
                float inv = rsqrtf(var + 1e-5f);
                y0v[j] = d0 * inv * sg1[lane] + sbe1[lane];
                y1v[j] = d1 * inv * sg1[lane + 32] + sbe1[lane + 32];
                float* sy = base_ + j * 448 + 64;
                sy[lane] = y0v[j]; sy[lane + 32] = y1v[j];
            }
            __syncwarp();

            #pragma unroll
            for (int mh = 0; mh < 2; mh++) {
                u64 acc2[4][2];
                #pragma unroll
                for (int j = 0; j < 4; j++)
                    #pragma unroll
                    for (int m = 0; m < 2; m++)
                        acc2[j][m] = pk_(sb1[lane + (mh*2+m)*64], sb1[lane + (mh*2+m)*64 + 32]);
                #pragma unroll 2
                for (int d = 0; d < 64; d++) {
                    const u64* row = (const u64*)(sW1P + d * 256);
                    u64 wv0 = row[(mh*2+0) * 32 + lane];
                    u64 wv1 = row[(mh*2+1) * 32 + lane];
                    #pragma unroll
                    for (int j = 0; j < 4; j++) {
                        float yd = base_[j * 448 + 64 + d];
                        u64 y2 = pk_(yd, yd);
                        acc2[j][0] = fma2_(y2, wv0, acc2[j][0]);
                        acc2[j][1] = fma2_(y2, wv1, acc2[j][1]);
                    }
                }
                #pragma unroll
                for (int j = 0; j < 4; j++) {
                    float* sgh = base_ + j * 448 + 128;
                    #pragma unroll
                    for (int m = 0; m < 2; m++) {
                        float2 f = unpk_(acc2[j][m]);
                        sgh[lane + (mh*2+m)*64]      = gelu_(f.x);
                        sgh[lane + (mh*2+m)*64 + 32] = gelu_(f.y);
                    }
                }
            }
            __syncwarp();

            u64 f2[4];
            #pragma unroll
            for (int j = 0; j < 4; j++) f2[j] = pk_(sb2[lane], sb2[lane + 32]);
            #pragma unroll 2
            for (int jj = 0; jj < 256; jj++) {
                u64 ww = *(const u64*)(sW2P + jj * 64 + lane * 2);
                #pragma unroll
                for (int j = 0; j < 4; j++) {
                    float gj = base_[j * 448 + 128 + jj];
                    f2[j] = fma2_(pk_(gj, gj), ww, f2[j]);
                }
            }

            #pragma unroll
            for (int j = 0; j < 4; j++) {
                int t = t0 + j;
                float2 ff = unpk_(f2[j]);
                float u0 = y0v[j] + ff.x, u1 = y1v[j] + ff.y;
                float m2 = wsum(u0 + u1) * (1.0f / 64.0f);
                float e0 = u0 - m2, e1 = u1 - m2;
                float v2 = wsum(e0 * e0 + e1 * e1) * (1.0f / 64.0f);
                float iv2 = rsqrtf(v2 + 1e-5f);
                float* sz = base_ + j * 448 + 384;
                sz[lane]      = e0 * iv2 * sg2[lane] + sbe2[lane];
                sz[lane + 32] = e1 * iv2 * sg2[lane + 32] + sbe2[lane + 32];

                float rpart = 0.f;
                if (lane < 8) {
                    int hh = lane;
                    const float4* kp = (const float4*)&g_ck[b][hh][t][0];
                    float4 ka = kp[0], kb = kp[1];
                    float k[8] = {ka.x, ka.y, ka.z, ka.w, kb.x, kb.y, kb.z, kb.w};
                    const float* N = sN + hh * 45;
                    float acc = N[0];
                    int idx = 1;
                    #pragma unroll
                    for (int i = 0; i < 8; i++) acc = fmaf(k[i], N[idx++], acc);
                    #pragma unroll
                    for (int i = 0; i < 8; i++) {
                        #pragma unroll
                        for (int jq = i; jq < 8; jq++) acc = fmaf(k[i] * k[jq], N[idx++], acc);
                    }
                    rpart = acc;
                }
                float recv_tot = wsum(rpart);
                __syncwarp();

                if (lane < 16) {
                    int i = lane, rb = i >> 2, cb = i & 3;
                    int tk = tok[b * 1024 + t];
                    float recv = recv_tot * (1.0f / 8192.0f);
                    float sv = semb[(size_t)tk * 16 + i] + recv * salp[i];
                    float sg = 1.0f / (1.0f + expf(-sv));
                    const float* Mr = M + ((size_t)(b * 1024 + t)) * 64;
                    float* Or = out + ((size_t)(b * 1024 + t)) * 64;
                    int base = 16 * rb + 2 * cb;
                    #pragma unroll
                    for (int e = 0; e < 4; e++) {
                        int r = e >> 1, c = e & 1;
                        int mi = base + 8 * r + c;
                        float bv = Mr[mi];
                        Or[mi] = bv + (sz[i * 4 + e] - bv) * sg;
                    }
                }
                __syncwarp();
            }
        }
    }
}

// ---------------- launch ----------------
extern "C" void kernel_launch(void* const* d_in, const int* in_sizes, int n_in,
                              void* d_out, int out_size)
{
    const float* M        = (const float*)d_in[0];
    const int*   tok      = (const int*)d_in[1];
    const float* Wqkv_blk = (const float*)d_in[2];
    const float* bqkv_blk = (const float*)d_in[3];
    const float* Wo_blk   = (const float*)d_in[4];
    const float* bo_blk   = (const float*)d_in[5];
    const float* Wqkv_c   = (const float*)d_in[6];
    const float* bqkv_c   = (const float*)d_in[7];
    const float* Wo_c     = (const float*)d_in[8];
    const float* bo_c     = (const float*)d_in[9];
    const float* W1       = (const float*)d_in[10];
    const float* b1       = (const float*)d_in[11];
    const float* W2       = (const float*)d_in[12];
    const float* b2       = (const float*)d_in[13];
    const float* g1       = (const float*)d_in[14];
    const float* be1      = (const float*)d_in[15];
    const float* g2       = (const float*)d_in[16];
    const float* be2      = (const float*)d_in[17];
    const float* semb     = (const float*)d_in[18];
    const float* alpha    = (const float*)d_in[19];
    float* out = (float*)d_out;

    static bool init_done = false;
    if (!init_done) {
        cudaFuncSetAttribute(k_all, cudaFuncAttributeMaxDynamicSharedMemorySize, SMEM_BYTES);
        init_done = true;
    }

    k_all<<<GRID, NTHR, SMEM_BYTES>>>(M, tok, Wqkv_blk, bqkv_blk, Wo_blk, bo_blk,
                                      Wqkv_c, bqkv_c, Wo_c, bo_c, W1, b1, W2, b2,
                                      g1, be1, g2, be2, semb, alpha, out);
}

// round 15
// speedup vs baseline: 1.0302x; 1.0302x over previous
#include <cuda_runtime.h>

#define TB 1024
#define NB 4
#define GRID 148
#define NTHR 512

typedef unsigned long long u64;

// ---------------- global scratch ----------------
#define CM_OFF 0          // cross K-moments (45 alphas x 12): 4*8*540 = 17280
#define CN_OFF 17280      // cross Q-moments: 4*8*45 = 1440
#define MOM_TOTAL 18720
__device__ float  g_mom[MOM_TOTAL];
__device__ float  g_bmp[128][60];          // blk partial moments (raw)
__device__ float4 g_bq4[NB][TB][16];       // blk q, [b][t][blk]
__device__ float  g_ab[NB][TB][64];
__device__ float  g_cq[NB][8][TB][8];
__device__ float  g_ck[NB][8][TB][8];
__device__ float  g_ao[NB][TB][64];

__device__ unsigned g_bar_cnt = 0;
__device__ unsigned g_bar_gen = 0;

__device__ __forceinline__ void grid_sync() {
    __syncthreads();
    if (threadIdx.x == 0) {
        unsigned gen;
        asm volatile("ld.global.acquire.gpu.u32 %0, [%1];" : "=r"(gen) : "l"(&g_bar_gen));
        __threadfence();
        unsigned prev;
        asm volatile("atom.global.release.gpu.add.u32 %0, [%1], %2;"
                     : "=r"(prev) : "l"(&g_bar_cnt), "r"(1u) : "memory");
        if (prev == GRID - 1) {
            asm volatile("st.global.relaxed.gpu.u32 [%0], %1;" :: "l"(&g_bar_cnt), "r"(0u) : "memory");
            asm volatile("st.global.release.gpu.u32 [%0], %1;" :: "l"(&g_bar_gen), "r"(gen + 1u) : "memory");
        } else {
            unsigned cur;
            do {
                asm volatile("ld.global.acquire.gpu.u32 %0, [%1];" : "=r"(cur) : "l"(&g_bar_gen));
            } while (cur == gen);
        }
    }
    __syncthreads();
}

#define GBAR(id, cnt) asm volatile("bar.sync %0, %1;" :: "r"(id), "r"(cnt) : "memory")

__device__ __forceinline__ u64 fma2_(u64 a, u64 b, u64 c) {
    u64 r; asm("fma.rn.f32x2 %0, %1, %2, %3;" : "=l"(r) : "l"(a), "l"(b), "l"(c)); return r;
}
__device__ __forceinline__ u64 mul2_(u64 a, u64 b) {
    u64 r; asm("mul.rn.f32x2 %0, %1, %2;" : "=l"(r) : "l"(a), "l"(b)); return r;
}
__device__ __forceinline__ u64 add2_(u64 a, u64 b) {
    u64 r; asm("add.rn.f32x2 %0, %1, %2;" : "=l"(r) : "l"(a), "l"(b)); return r;
}
__device__ __forceinline__ float2 unpk_(u64 v) {
    float2 r; asm("mov.b64 {%0, %1}, %2;" : "=f"(r.x), "=f"(r.y) : "l"(v)); return r;
}
__device__ __forceinline__ u64 pk_(float lo, float hi) {
    u64 r; asm("mov.b64 %0, {%1, %2};" : "=l"(r) : "f"(lo), "f"(hi)); return r;
}
__device__ __forceinline__ float wsum(float v) {
    #pragma unroll
    for (int o = 16; o > 0; o >>= 1) v += __shfl_xor_sync(0xffffffffu, v, o);
    return v;
}
__device__ __forceinline__ float gelu_(float x) {
    return 0.5f * x * (1.0f + erff(x * 0.7071067811865476f));
}
__device__ __forceinline__ void cross_alpha2(int alpha, int& deg, int& i0, int& j0, float& coef) {
    deg = 0; i0 = 0; j0 = 0; coef = 1.f;
    if (alpha == 0) { deg = 0; }
    else if (alpha < 9) { deg = 1; i0 = alpha - 1; }
    else {
        deg = 2; int r = alpha - 9; int ii = 0;
        while (r >= 8 - ii) { r -= 8 - ii; ii++; }
        i0 = ii; j0 = ii + r;
        coef = (i0 == j0) ? 0.5f : 1.f;
    }
}

// smem (floats): [0,36864) epi weights | [36864,37520) small | [37520,37880) sN | [37880,+16704) phase scratch
#define PS_OFF 37880
#define SCRATCH_FLOATS 16704
#define SMEM_FLOATS (PS_OFF + SCRATCH_FLOATS)
#define SMEM_BYTES (SMEM_FLOATS * 4)

#define KPS 522

__global__ void __launch_bounds__(NTHR, 1)
k_all(const float* __restrict__ M,
      const int* __restrict__ tok,
      const float* __restrict__ Wqkv_blk, const float* __restrict__ bqkv_blk,
      const float* __restrict__ Wo_blk,   const float* __restrict__ bo_blk,
      const float* __restrict__ Wqkv_c,   const float* __restrict__ bqkv_c,
      const float* __restrict__ Woc,      const float* __restrict__ boc,
      const float* __restrict__ W1,       const float* __restrict__ b1,
      const float* __restrict__ W2,       const float* __restrict__ b2,
      const float* __restrict__ g1,       const float* __restrict__ be1,
      const float* __restrict__ g2,       const float* __restrict__ be2,
      const float* __restrict__ semb,     const float* __restrict__ alpha,
      float* __restrict__ out)
{
    extern __shared__ float sm[];
    const int tid = threadIdx.x;
    const int bid = blockIdx.x;

    float* sWoP = sm;
    float* sW1P = sm + 4096;
    float* sW2P = sm + 20480;
    float* sSm  = sm + 36864;
    float* sboc = sSm;        float* sb1  = sSm + 64;  float* sb2  = sSm + 320;
    float* sg1  = sSm + 384;  float* sbe1 = sSm + 448; float* sg2  = sSm + 512;
    float* sbe2 = sSm + 576;  float* salp = sSm + 640;
    float* sN = sm + 37520;
    float* ps = sm + PS_OFF;

    // ---------- prologue: epilogue weights ----------
    for (int i = tid; i < 4096; i += NTHR) {
        int d = i >> 6, j = i & 63;
        sWoP[j * 64 + (d & 31) * 2 + (d >> 5)] = Woc[i];
    }
    for (int i = tid; i < 16384; i += NTHR) {
        int j = i >> 6, d = i & 63;
        sW1P[d * 256 + ((j >> 6) * 32 + (j & 31)) * 2 + ((j >> 5) & 1)] = W1[i];
    }
    for (int i = tid; i < 16384; i += NTHR) {
        int d = i >> 8, j = i & 255;
        sW2P[j * 64 + (d & 31) * 2 + (d >> 5)] = W2[i];
    }
    for (int i = tid; i < 64; i += NTHR) { sboc[i] = boc[i]; sb2[i] = b2[i];
                                           sg1[i] = g1[i]; sbe1[i] = be1[i];
                                           sg2[i] = g2[i]; sbe2[i] = be2[i]; }
    if (tid < 256) sb1[tid] = b1[tid];
    if (tid < 16) salp[tid] = alpha[tid];

    // ================= Phase A: blk QKV + partial moments. 128 CTAs =================
    if (bid < 128) {
        int b = bid >> 5, blk = (bid >> 1) & 15, half = bid & 1;
        float* sW  = ps;
        float* sB  = ps + 768;
        float* sKP = ps + 960;
        float* sPart = ps + 960 + 8 * KPS;

        for (int i = tid; i < 768; i += NTHR) sW[i] = Wqkv_blk[i];
        if (tid < 192) sB[tid] = bqkv_blk[tid];
        __syncthreads();

        int rb = blk >> 2, cb = blk & 3;
        int basec = 16 * rb + 2 * cb;
        const float* W  = sW + blk * 48;
        const float* bb = sB + blk * 12;
        const float qs = 0.70710678118654752f;

        int t = half * 512 + tid;
        {
            const float* Mr = M + ((size_t)(b * 1024 + t)) * 64;
            float2 xa = *(const float2*)(Mr + basec);
            float2 xb = *(const float2*)(Mr + basec + 8);
            float x0 = xa.x, x1 = xa.y, x2 = xb.x, x3 = xb.y;
            float o[12];
            #pragma unroll
            for (int j = 0; j < 12; j++)
                o[j] = fmaf(W[j*4], x0, fmaf(W[j*4+1], x1, fmaf(W[j*4+2], x2, fmaf(W[j*4+3], x3, bb[j]))));
            g_bq4[b][t][blk] = make_float4(o[0]*qs, o[1]*qs, o[2]*qs, o[3]*qs);
            #pragma unroll
            for (int c = 0; c < 4; c++) {
                sKP[c * KPS + tid]       = o[4 + c];
                sKP[(4 + c) * KPS + tid] = o[8 + c];
            }
        }
        __syncthreads();

        {
            int sub = tid >> 6, u = tid & 63;
            if (u < 60) {
                int h = u / 30, rem = u % 30, al = rem / 3, g = rem % 3;
                const int A_[10] = {0,1,0,2,1,0,3,2,1,0};
                const int B_[10] = {0,0,1,0,1,2,0,1,2,3};
                int a = A_[al], be = B_[al], ab = a + be;
                const float* k0base = sKP + (2*h) * KPS;
                const float* k1base = sKP + (2*h + 1) * KPS;
                const float* vbase  = (g < 2) ? (sKP + (4 + 2*h + g) * KPS) : k0base;
                const u64 ONE2 = pk_(1.f, 1.f);
                u64 acc2 = 0ull;
                int p0 = sub * 32;
                #pragma unroll 4
                for (int p = p0; p < p0 + 32; p++) {
                    u64 K0 = *(const u64*)(k0base + 2 * p);
                    u64 K1 = *(const u64*)(k1base + 2 * p);
                    u64 f0 = (0 < a) ? K0 : ((0 < ab) ? K1 : ONE2);
                    u64 f1 = (1 < a) ? K0 : ((1 < ab) ? K1 : ONE2);
                    u64 f2 = (2 < a) ? K0 : ((2 < ab) ? K1 : ONE2);
                    u64 m2 = mul2_(mul2_(f0, f1), f2);
                    if (g == 2) acc2 = add2_(acc2, m2);
                    else        acc2 = fma2_(m2, *(const u64*)(vbase + 2 * p), acc2);
                }
                float2 f = unpk_(acc2);
                sPart[u * 9 + sub] = f.x + f.y;
            }
        }
        __syncthreads();
        if (tid < 60) {
            float s = 0.f;
            #pragma unroll
            for (int k = 0; k < 8; k++) s += sPart[tid * 9 + k];
            g_bmp[bid][tid] = s;
        }
    } else {
        for (int i = (bid - 128) * NTHR + tid; i < MOM_TOTAL; i += 20 * NTHR)
            g_mom[i] = 0.f;
    }
    grid_sync();   // bar1

    // ================= Phase B: blk eval + cross QKV + K-moments. 128 CTAs x 32 tokens =================
    if (bid < 128) {
        float* sWq   = ps;
        float* sBias = ps + 12288;
        float* R     = ps + 12480;
        float* sMomB = R;                    // 16 x 61
        float4* sBQ  = (float4*)(R + 976);

        for (int i = tid; i < 12288; i += NTHR) sWq[i] = Wqkv_c[i];
        if (tid < 192) sBias[tid] = bqkv_c[tid];

        int b  = bid >> 5;
        int t0 = (bid * 32) & 1023;

        {
            const int A_[10] = {0,1,0,2,1,0,3,2,1,0};
            const int B_[10] = {0,0,1,0,1,2,0,1,2,3};
            const float invf[4] = {1.f, 1.f, 0.5f, 1.f/6.f};
            for (int i = tid; i < 960; i += NTHR) {
                int blkI = i / 60, u = i % 60;
                int al = (u % 30) / 3;
                float coef = invf[A_[al]] * invf[B_[al]];
                sMomB[blkI * 61 + u] =
                    (g_bmp[(b*16 + blkI)*2][u] + g_bmp[(b*16 + blkI)*2 + 1][u]) * coef;
            }
        }
        sBQ[tid] = g_bq4[b][t0 + (tid >> 4)][tid & 15];
        __syncthreads();

        {
            int token = tid >> 4, blk = tid & 15;
            float4 q4 = sBQ[tid];
            const float* mom = sMomB + blk * 61;
            float y[4];
            #pragma unroll
            for (int h = 0; h < 2; h++) {
                float q0 = h ? q4.z : q4.x;
                float q1 = h ? q4.w : q4.y;
                float p0[4], p1[4];
                p0[0] = 1.f; p1[0] = 1.f;
                #pragma unroll
                for (int e = 1; e < 4; e++) { p0[e] = p0[e-1] * q0; p1[e] = p1[e-1] * q1; }
                float O0 = 0.f, O1 = 0.f, Z = 0.f;
                int idx = 0;
                #pragma unroll
                for (int n = 0; n <= 3; n++) {
                    #pragma unroll
                    for (int aa = n; aa >= 0; aa--) {
                        float m = p0[aa] * p1[n - aa];
                        const float* r = mom + h * 30 + idx * 3;
                        O0 = fmaf(m, r[0], O0);
                        O1 = fmaf(m, r[1], O1);
                        Z  = fmaf(m, r[2], Z);
                        idx++;
                    }
                }
                float zi = 1.f / Z;
                y[h*2 + 0] = O0 * zi;
                y[h*2 + 1] = O1 * zi;
            }
            const float* W  = Wo_blk + blk * 16;
            const float* bb = bo_blk + blk * 4;
            float4 r;
            r.x = __ldg(&bb[0]) + __ldg(&W[0])*y[0]  + __ldg(&W[1])*y[1]  + __ldg(&W[2])*y[2]  + __ldg(&W[3])*y[3];
            r.y = __ldg(&bb[1]) + __ldg(&W[4])*y[0]  + __ldg(&W[5])*y[1]  + __ldg(&W[6])*y[2]  + __ldg(&W[7])*y[3];
            r.z = __ldg(&bb[2]) + __ldg(&W[8])*y[0]  + __ldg(&W[9])*y[1]  + __ldg(&W[10])*y[2] + __ldg(&W[11])*y[3];
            r.w = __ldg(&bb[3]) + __ldg(&W[12])*y[0] + __ldg(&W[13])*y[1] + __ldg(&W[14])*y[2] + __ldg(&W[15])*y[3];
            *(float4*)&g_ab[b][t0 + token][blk * 4] = r;
        }
        __syncthreads();

        float (*kT)[33] = (float(*)[33])R;
        float (*vT)[33] = (float(*)[33])(R + 2112);
        {
            int lane32 = tid & 31;
            int slice  = tid >> 5;
            int t = t0 + lane32;

            u64 x2[32];
            {
                const ulonglong2* xr = (const ulonglong2*)&g_ab[b][t][0];
                #pragma unroll
                for (int i = 0; i < 16; i++) { ulonglong2 v = xr[i]; x2[2*i] = v.x; x2[2*i+1] = v.y; }
            }
            const float qsc = 0.35355339059327373f;
            #pragma unroll
            for (int jj = 0; jj < 12; jj++) {
                int j = slice * 12 + jj;
                const ulonglong2* w4 = (const ulonglong2*)(sWq + j * 64);
                u64 a0 = 0ull, a1 = 0ull;
                #pragma unroll
                for (int d = 0; d < 16; d++) {
                    ulonglong2 w = w4[d];
                    a0 = fma2_(x2[2*d],     w.x, a0);
                    a1 = fma2_(x2[2*d + 1], w.y, a1);
                }
                float2 fa = unpk_(a0), fb = unpk_(a1);
                float val = (fa.x + fa.y) + (fb.x + fb.y) + sBias[j];
                if (j < 64) {
                    g_cq[b][j >> 3][t][j & 7] = val * qsc;
                } else if (j < 128) {
                    int c = j - 64;
                    g_ck[b][c >> 3][t][c & 7] = val;
                    kT[c][lane32] = val;
                } else {
                    vT[j - 128][lane32] = val;
                }
            }
        }
        __syncthreads();

        if (tid < 360) {
            int h = tid / 45, al = tid % 45;
            int deg, i0, j0; float coef;
            cross_alpha2(al, deg, i0, j0, coef);
            float acc[9];
            #pragma unroll
            for (int g = 0; g < 9; g++) acc[g] = 0.f;
            #pragma unroll 4
            for (int k = 0; k < 32; k++) {
                float m = 1.f;
                if (deg >= 1) m = kT[h*8 + i0][k];
                if (deg >= 2) m *= kT[h*8 + j0][k];
                #pragma unroll
                for (int d = 0; d < 8; d++)
                    acc[d] = fmaf(m, vT[h*8 + d][k], acc[d]);
                acc[8] += m;
            }
            float* dst = &g_mom[CM_OFF + (b*8 + h)*540 + al * 12];
            #pragma unroll
            for (int g = 0; g < 9; g++) atomicAdd(dst + g, acc[g] * coef);
        }
    }
    grid_sync();   // bar2

    // ================= Phase C: cross eval + Q-moments. 1024 items, 8 groups x 64 =================
    if (bid < 128) {
        int g = tid >> 6, gt = tid & 63;
        float* base_ = ps + g * 836;
        float* sM = base_;
        float (*sQT)[33] = (float(*)[33])(base_ + 540);
        float* sZ = base_ + 804;
        int item = bid * 8 + g;
        int qc = item & 31, h = (item >> 5) & 7, b = item >> 8;

        for (int i = gt; i < 135; i += 64)
            ((float4*)sM)[i] = ((const float4*)&g_mom[CM_OFF + (b*8 + h)*540])[i];

        int t = qc * 32 + (gt & 31);
        float q[8];
        if (gt < 32) {
            const float4* qp = (const float4*)&g_cq[b][h][t][0];
            float4 a = qp[0], c = qp[1];
            q[0]=a.x; q[1]=a.y; q[2]=a.z; q[3]=a.w; q[4]=c.x; q[5]=c.y; q[6]=c.z; q[7]=c.w;
            #pragma unroll
            for (int i = 0; i < 8; i++) sQT[i][gt] = q[i];
        }
        GBAR(1 + g, 64);

        if (gt < 32) {
            float a0=0,a1=0,a2=0,a3=0,a4=0,a5=0,a6=0,a7=0,a8=0;
            int idx = 0;
#define FMA9(MV) { float m_ = (MV); const float4* r_ = (const float4*)(sM + idx * 12); \
    float4 ra = r_[0], rb = r_[1], rc = r_[2]; \
    a0 = fmaf(m_, ra.x, a0); a1 = fmaf(m_, ra.y, a1); a2 = fmaf(m_, ra.z, a2); a3 = fmaf(m_, ra.w, a3); \
    a4 = fmaf(m_, rb.x, a4); a5 = fmaf(m_, rb.y, a5); a6 = fmaf(m_, rb.z, a6); a7 = fmaf(m_, rb.w, a7); \
    a8 = fmaf(m_, rc.x, a8); idx++; }
            FMA9(1.f);
            #pragma unroll
            for (int i = 0; i < 8; i++) FMA9(q[i]);
            #pragma unroll
            for (int i = 0; i < 8; i++) {
                #pragma unroll
                for (int j = i; j < 8; j++) FMA9(q[i] * q[j]);
            }
#undef FMA9
            float zi = 1.f / a8;
            float4* dst = (float4*)&g_ao[b][t][h * 8];
            dst[0] = make_float4(a0*zi, a1*zi, a2*zi, a3*zi);
            dst[1] = make_float4(a4*zi, a5*zi, a6*zi, a7*zi);
            sZ[gt] = zi;
        }
        GBAR(1 + g, 64);

        if (gt < 45) {
            int deg, i0, j0; float coef;
            cross_alpha2(gt, deg, i0, j0, coef);
            float acc = 0.f;
            #pragma unroll 4
            for (int k = 0; k < 32; k++) {
                float m = sZ[k];
                if (deg >= 1) m *= sQT[i0][k];
                if (deg >= 2) m *= sQT[j0][k];
                acc += m;
            }
            atomicAdd(&g_mom[CN_OFF + (b*8 + h)*45 + gt], acc * coef);
        }
    }
    grid_sync();   // bar3

    // ================= Phase D: epilogue + fused recv. 128 CTAs, 8 warps x 4 tokens =================
    // token-interleaved activation scratch: one LDS.128 broadcast feeds all 4 tokens
    if (bid < 128) {
        int bblk = bid >> 5;
        for (int i = tid; i < 360; i += NTHR)
            sN[i] = g_mom[CN_OFF + bblk * 360 + i];
        __syncthreads();

        int w = tid >> 5, lane = tid & 31;
        if (w < 8) {
            float* base_ = ps + w * 1792;
            float* ao4 = base_;           // [64][4]
            float* y4  = base_ + 256;     // [64][4]
            float* gh4 = base_ + 512;     // [256][4]
            float* z4  = base_ + 1536;    // [64][4]
            int b = (bid * 32) >> 10;
            int t0 = (bid * 32 + w * 4) & 1023;

            #pragma unroll
            for (int j = 0; j < 4; j++) {
                const float* aor = &g_ao[b][t0 + j][0];
                ao4[lane * 4 + j]        = aor[lane];
                ao4[(lane + 32) * 4 + j] = aor[lane + 32];
            }
            __syncwarp();

            // Wo projection: 1 weight LDS.64 + 1 activation LDS.128 -> 4 fma2
            u64 co2[4];
            #pragma unroll
            for (int j = 0; j < 4; j++) co2[j] = pk_(sboc[lane], sboc[lane + 32]);
            #pragma unroll 2
            for (int jj = 0; jj < 64; jj++) {
                u64 ww = *(const u64*)(sWoP + jj * 64 + lane * 2);
                float4 a4 = *(const float4*)(ao4 + jj * 4);
                co2[0] = fma2_(pk_(a4.x, a4.x), ww, co2[0]);
                co2[1] = fma2_(pk_(a4.y, a4.y), ww, co2[1]);
                co2[2] = fma2_(pk_(a4.z, a4.z), ww, co2[2]);
                co2[3] = fma2_(pk_(a4.w, a4.w), ww, co2[3]);
            }

            float y0v[4], y1v[4];
            #pragma unroll
            for (int j = 0; j < 4; j++) {
                float2 co = unpk_(co2[j]);
                float x0 = g_ab[b][t0 + j][lane] + co.x;
                float x1 = g_ab[b][t0 + j][lane + 32] + co.y;
                float mean = wsum(x0 + x1) * (1.0f / 64.0f);
                float d0 = x0 - mean, d1 = x1 - mean;
                float var = wsum(d0 * d0 + d1 * d1) * (1.0f / 64.0f);
                float inv = rsqrtf(var + 1e-5f);
                y0v[j] = d0 * inv * sg1[lane] + sbe1[lane];
                y1v[j] = d1 * inv * sg1[lane + 32] + sbe1[lane + 32];
                y4[lane * 4 + j]        = y0v[j];
                y4[(lane + 32) * 4 + j] = y1v[j];
            }
            __syncwarp();

            // FFN1: weights read once per (d, m), activations via LDS.128 broadcast
            #pragma unroll
            for (int mh = 0; mh < 2; mh++) {
                u64 acc2[4][2];
                #pragma unroll
                for (int j = 0; j < 4; j++)
                    #pragma unroll
                    for (int m = 0; m < 2; m++)
                        acc2[j][m] = pk_(sb1[lane + (mh*2+m)*64], sb1[lane + (mh*2+m)*64 + 32]);
                #pragma unroll 2
                for (int d = 0; d < 64; d++) {
                    const u64* row = (const u64*)(sW1P + d * 256);
                    u64 wv0 = row[(mh*2+0) * 32 + lane];
                    u64 wv1 = row[(mh*2+1) * 32 + lane];
                    float4 yd4 = *(const float4*)(y4 + d * 4);
                    u64 yp[4] = {pk_(yd4.x, yd4.x), pk_(yd4.y, yd4.y), pk_(yd4.z, yd4.z), pk_(yd4.w, yd4.w)};
                    #pragma unroll
                    for (int j = 0; j < 4; j++) {
                        acc2[j][0] = fma2_(yp[j], wv0, acc2[j][0]);
                        acc2[j][1] = fma2_(yp[j], wv1, acc2[j][1]);
                    }
                }
                #pragma unroll
                for (int j = 0; j < 4; j++) {
                    #pragma unroll
                    for (int m = 0; m < 2; m++) {
                        float2 f = unpk_(acc2[j][m]);
                        gh4[(lane + (mh*2+m)*64) * 4 + j]        = gelu_(f.x);
                        gh4[(lane + (mh*2+m)*64 + 32) * 4 + j]   = gelu_(f.y);
                    }
                }
            }
            __syncwarp();

            // FFN2: 1 weight LDS.64 + 1 activation LDS.128 -> 4 fma2
            u64 f2[4];
            #pragma unroll
            for (int j = 0; j < 4; j++) f2[j] = pk_(sb2[lane], sb2[lane + 32]);
            #pragma unroll 2
            for (int jj = 0; jj < 256; jj++) {
                u64 ww = *(const u64*)(sW2P + jj * 64 + lane * 2);
                float4 g4 = *(const float4*)(gh4 + jj * 4);
                f2[0] = fma2_(pk_(g4.x, g4.x), ww, f2[0]);
                f2[1] = fma2_(pk_(g4.y, g4.y), ww, f2[1]);
                f2[2] = fma2_(pk_(g4.z, g4.z), ww, f2[2]);
                f2[3] = fma2_(pk_(g4.w, g4.w), ww, f2[3]);
            }

            #pragma unroll
            for (int j = 0; j < 4; j++) {
                int t = t0 + j;
                float2 ff = unpk_(f2[j]);
                float u0 = y0v[j] + ff.x, u1 = y1v[j] + ff.y;
                float m2 = wsum(u0 + u1) * (1.0f / 64.0f);
                float e0 = u0 - m2, e1 = u1 - m2;
                float v2 = wsum(e0 * e0 + e1 * e1) * (1.0f / 64.0f);
                float iv2 = rsqrtf(v2 + 1e-5f);
                z4[lane * 4 + j]        = e0 * iv2 * sg2[lane] + sbe2[lane];
                z4[(lane + 32) * 4 + j] = e1 * iv2 * sg2[lane + 32] + sbe2[lane + 32];

                float rpart = 0.f;
                if (lane < 8) {
                    int hh = lane;
                    const float4* kp = (const float4*)&g_ck[b][hh][t][0];
                    float4 ka = kp[0], kb = kp[1];
                    float k[8] = {ka.x, ka.y, ka.z, ka.w, kb.x, kb.y, kb.z, kb.w};
                    const float* N = sN + hh * 45;
                    float acc = N[0];
                    int idx = 1;
                    #pragma unroll
                    for (int i = 0; i < 8; i++) acc = fmaf(k[i], N[idx++], acc);
                    #pragma unroll
                    for (int i = 0; i < 8; i++) {
                        #pragma unroll
                        for (int jq = i; jq < 8; jq++) acc = fmaf(k[i] * k[jq], N[idx++], acc);
                    }
                    rpart = acc;
                }
                float recv_tot = wsum(rpart);
                __syncwarp();

                if (lane < 16) {
                    int i = lane, rb = i >> 2, cb = i & 3;
                    int tk = tok[b * 1024 + t];
                    float recv = recv_tot * (1.0f / 8192.0f);
                    float sv = semb[(size_t)tk * 16 + i] + recv * salp[i];
                    float sg = 1.0f / (1.0f + expf(-sv));
                    const float* Mr = M + ((size_t)(b * 1024 + t)) * 64;
                    float* Or = out + ((size_t)(b * 1024 + t)) * 64;
                    int base = 16 * rb + 2 * cb;
                    #pragma unroll
                    for (int e = 0; e < 4; e++) {
                        int r = e >> 1, c = e & 1;
                        int mi = base + 8 * r + c;
                        float bv = Mr[mi];
                        Or[mi] = bv + (z4[(i * 4 + e) * 4 + j] - bv) * sg;
                    }
                }
                __syncwarp();
            }
        }
    }
}

// ---------------- launch ----------------
extern "C" void kernel_launch(void* const* d_in, const int* in_sizes, int n_in,
                              void* d_out, int out_size)
{
    const float* M        = (const float*)d_in[0];
    const int*   tok      = (const int*)d_in[1];
    const float* Wqkv_blk = (const float*)d_in[2];
    const float* bqkv_blk = (const float*)d_in[3];
    const float* Wo_blk   = (const float*)d_in[4];
    const float* bo_blk   = (const float*)d_in[5];
    const float* Wqkv_c   = (const float*)d_in[6];
    const float* bqkv_c   = (const float*)d_in[7];
    const float* Wo_c     = (const float*)d_in[8];
    const float* bo_c     = (const float*)d_in[9];
    const float* W1       = (const float*)d_in[10];
    const float* b1       = (const float*)d_in[11];
    const float* W2       = (const float*)d_in[12];
    const float* b2       = (const float*)d_in[13];
    const float* g1       = (const float*)d_in[14];
    const float* be1      = (const float*)d_in[15];
    const float* g2       = (const float*)d_in[16];
    const float* be2      = (const float*)d_in[17];
    const float* semb     = (const float*)d_in[18];
    const float* alpha    = (const float*)d_in[19];
    float* out = (float*)d_out;

    static bool init_done = false;
    if (!init_done) {
        cudaFuncSetAttribute(k_all, cudaFuncAttributeMaxDynamicSharedMemorySize, SMEM_BYTES);
        init_done = true;
    }

    k_all<<<GRID, NTHR, SMEM_BYTES>>>(M, tok, Wqkv_blk, bqkv_blk, Wo_blk, bo_blk,
                                      Wqkv_c, bqkv_c, Wo_c, bo_c, W1, b1, W2, b2,
                                      g1, be1, g2, be2, semb, alpha, out);
}

// round 16
// speedup vs baseline: 1.2294x; 1.1934x over previous
#include <cuda_runtime.h>

#define TB 1024
#define NB 4
#define GRID 148
#define NTHR 512

typedef unsigned long long u64;

// ---------------- global scratch ----------------
#define CM_OFF 0
#define CN_OFF 17280
#define MOM_TOTAL 18720
__device__ float  g_mom[MOM_TOTAL];
__device__ float  g_bmp[128][60];
__device__ float4 g_bq4[NB][TB][16];
__device__ float  g_ab[NB][TB][64];
__device__ float  g_cq[NB][8][TB][8];
__device__ float  g_ck[NB][8][TB][8];
__device__ float  g_ao[NB][TB][64];

__device__ unsigned g_bar_cnt = 0;
__device__ unsigned g_bar_gen = 0;

__device__ __forceinline__ void grid_sync() {
    __syncthreads();
    if (threadIdx.x == 0) {
        unsigned gen;
        asm volatile("ld.global.acquire.gpu.u32 %0, [%1];" : "=r"(gen) : "l"(&g_bar_gen));
        __threadfence();
        unsigned prev;
        asm volatile("atom.global.release.gpu.add.u32 %0, [%1], %2;"
                     : "=r"(prev) : "l"(&g_bar_cnt), "r"(1u) : "memory");
        if (prev == GRID - 1) {
            asm volatile("st.global.relaxed.gpu.u32 [%0], %1;" :: "l"(&g_bar_cnt), "r"(0u) : "memory");
            asm volatile("st.global.release.gpu.u32 [%0], %1;" :: "l"(&g_bar_gen), "r"(gen + 1u) : "memory");
        } else {
            unsigned cur;
            do {
                asm volatile("ld.global.acquire.gpu.u32 %0, [%1];" : "=r"(cur) : "l"(&g_bar_gen));
            } while (cur == gen);
        }
    }
    __syncthreads();
}

#define GBAR(id, cnt) asm volatile("bar.sync %0, %1;" :: "r"(id), "r"(cnt) : "memory")

__device__ __forceinline__ u64 fma2_(u64 a, u64 b, u64 c) {
    u64 r; asm("fma.rn.f32x2 %0, %1, %2, %3;" : "=l"(r) : "l"(a), "l"(b), "l"(c)); return r;
}
__device__ __forceinline__ u64 mul2_(u64 a, u64 b) {
    u64 r; asm("mul.rn.f32x2 %0, %1, %2;" : "=l"(r) : "l"(a), "l"(b)); return r;
}
__device__ __forceinline__ u64 add2_(u64 a, u64 b) {
    u64 r; asm("add.rn.f32x2 %0, %1, %2;" : "=l"(r) : "l"(a), "l"(b)); return r;
}
__device__ __forceinline__ float2 unpk_(u64 v) {
    float2 r; asm("mov.b64 {%0, %1}, %2;" : "=f"(r.x), "=f"(r.y) : "l"(v)); return r;
}
__device__ __forceinline__ u64 pk_(float lo, float hi) {
    u64 r; asm("mov.b64 %0, {%1, %2};" : "=l"(r) : "f"(lo), "f"(hi)); return r;
}
__device__ __forceinline__ float wsum(float v) {
    #pragma unroll
    for (int o = 16; o > 0; o >>= 1) v += __shfl_xor_sync(0xffffffffu, v, o);
    return v;
}
__device__ __forceinline__ float gelu_(float x) {
    return 0.5f * x * (1.0f + erff(x * 0.7071067811865476f));
}
__device__ __forceinline__ void cross_alpha2(int alpha, int& deg, int& i0, int& j0, float& coef) {
    deg = 0; i0 = 0; j0 = 0; coef = 1.f;
    if (alpha == 0) { deg = 0; }
    else if (alpha < 9) { deg = 1; i0 = alpha - 1; }
    else {
        deg = 2; int r = alpha - 9; int ii = 0;
        while (r >= 8 - ii) { r -= 8 - ii; ii++; }
        i0 = ii; j0 = ii + r;
        coef = (i0 == j0) ? 0.5f : 1.f;
    }
}

#define PS_OFF 37880
#define SCRATCH_FLOATS 16704
#define SMEM_FLOATS (PS_OFF + SCRATCH_FLOATS)
#define SMEM_BYTES (SMEM_FLOATS * 4)

#define KPS 522

__global__ void __launch_bounds__(NTHR, 1)
k_all(const float* __restrict__ M,
      const int* __restrict__ tok,
      const float* __restrict__ Wqkv_blk, const float* __restrict__ bqkv_blk,
      const float* __restrict__ Wo_blk,   const float* __restrict__ bo_blk,
      const float* __restrict__ Wqkv_c,   const float* __restrict__ bqkv_c,
      const float* __restrict__ Woc,      const float* __restrict__ boc,
      const float* __restrict__ W1,       const float* __restrict__ b1,
      const float* __restrict__ W2,       const float* __restrict__ b2,
      const float* __restrict__ g1,       const float* __restrict__ be1,
      const float* __restrict__ g2,       const float* __restrict__ be2,
      const float* __restrict__ semb,     const float* __restrict__ alpha,
      float* __restrict__ out)
{
    extern __shared__ float sm[];
    const int tid = threadIdx.x;
    const int bid = blockIdx.x;

    float* sWoP = sm;
    float* sW1P = sm + 4096;
    float* sW2P = sm + 20480;
    float* sSm  = sm + 36864;
    float* sboc = sSm;        float* sb1  = sSm + 64;  float* sb2  = sSm + 320;
    float* sg1  = sSm + 384;  float* sbe1 = sSm + 448; float* sg2  = sSm + 512;
    float* sbe2 = sSm + 576;  float* salp = sSm + 640;
    float* sN = sm + 37520;
    float* ps = sm + PS_OFF;

    // ---------- prologue: epilogue weights, XOR-swizzled (2-way max conflict) ----------
    // sWoP[j][pos^s(j)] : pos = 2*(d&31) + (d>>5), s(j) = 2*(j&31)
    for (int i = tid; i < 4096; i += NTHR) {
        int d = i >> 6, j = i & 63;
        int pos = ((d & 31) * 2 + (d >> 5)) ^ ((j & 31) * 2);
        sWoP[j * 64 + pos] = Woc[i];
    }
    // sW1P[d][q^s(d)] : q = ((j>>6)*32 + (j&31))*2 + ((j>>5)&1), s(d) = 2*(d&31)
    for (int i = tid; i < 16384; i += NTHR) {
        int j = i >> 6, d = i & 63;
        int q = ((j >> 6) * 32 + (j & 31)) * 2 + ((j >> 5) & 1);
        sW1P[d * 256 + (q ^ ((d & 31) * 2))] = W1[i];
    }
    // sW2P[j][pos^s(j)] : pos = 2*(d&31) + (d>>5), s(j) = 2*(j&31)
    for (int i = tid; i < 16384; i += NTHR) {
        int d = i >> 8, j = i & 255;
        int pos = ((d & 31) * 2 + (d >> 5)) ^ ((j & 31) * 2);
        sW2P[j * 64 + pos] = W2[i];
    }
    for (int i = tid; i < 64; i += NTHR) { sboc[i] = boc[i]; sb2[i] = b2[i];
                                           sg1[i] = g1[i]; sbe1[i] = be1[i];
                                           sg2[i] = g2[i]; sbe2[i] = be2[i]; }
    if (tid < 256) sb1[tid] = b1[tid];
    if (tid < 16) salp[tid] = alpha[tid];

    // ================= Phase A: blk QKV + partial moments. 128 CTAs =================
    if (bid < 128) {
        int b = bid >> 5, blk = (bid >> 1) & 15, half = bid & 1;
        float* sW  = ps;
        float* sB  = ps + 768;
        float* sKP = ps + 960;
        float* sPart = ps + 960 + 8 * KPS;

        for (int i = tid; i < 768; i += NTHR) sW[i] = Wqkv_blk[i];
        if (tid < 192) sB[tid] = bqkv_blk[tid];
        __syncthreads();

        int rb = blk >> 2, cb = blk & 3;
        int basec = 16 * rb + 2 * cb;
        const float* W  = sW + blk * 48;
        const float* bb = sB + blk * 12;
        const float qs = 0.70710678118654752f;

        int t = half * 512 + tid;
        {
            const float* Mr = M + ((size_t)(b * 1024 + t)) * 64;
            float2 xa = *(const float2*)(Mr + basec);
            float2 xb = *(const float2*)(Mr + basec + 8);
            float x0 = xa.x, x1 = xa.y, x2 = xb.x, x3 = xb.y;
            float o[12];
            #pragma unroll
            for (int j = 0; j < 12; j++)
                o[j] = fmaf(W[j*4], x0, fmaf(W[j*4+1], x1, fmaf(W[j*4+2], x2, fmaf(W[j*4+3], x3, bb[j]))));
            g_bq4[b][t][blk] = make_float4(o[0]*qs, o[1]*qs, o[2]*qs, o[3]*qs);
            #pragma unroll
            for (int c = 0; c < 4; c++) {
                sKP[c * KPS + tid]       = o[4 + c];
                sKP[(4 + c) * KPS + tid] = o[8 + c];
            }
        }
        __syncthreads();

        {
            int sub = tid >> 6, u = tid & 63;
            if (u < 60) {
                int h = u / 30, rem = u % 30, al = rem / 3, g = rem % 3;
                const int A_[10] = {0,1,0,2,1,0,3,2,1,0};
                const int B_[10] = {0,0,1,0,1,2,0,1,2,3};
                int a = A_[al], be = B_[al], ab = a + be;
                const float* k0base = sKP + (2*h) * KPS;
                const float* k1base = sKP + (2*h + 1) * KPS;
                const float* vbase  = (g < 2) ? (sKP + (4 + 2*h + g) * KPS) : k0base;
                const u64 ONE2 = pk_(1.f, 1.f);
                u64 acc2 = 0ull;
                int p0 = sub * 32;
                #pragma unroll 4
                for (int p = p0; p < p0 + 32; p++) {
                    u64 K0 = *(const u64*)(k0base + 2 * p);
                    u64 K1 = *(const u64*)(k1base + 2 * p);
                    u64 f0 = (0 < a) ? K0 : ((0 < ab) ? K1 : ONE2);
                    u64 f1 = (1 < a) ? K0 : ((1 < ab) ? K1 : ONE2);
                    u64 f2 = (2 < a) ? K0 : ((2 < ab) ? K1 : ONE2);
                    u64 m2 = mul2_(mul2_(f0, f1), f2);
                    if (g == 2) acc2 = add2_(acc2, m2);
                    else        acc2 = fma2_(m2, *(const u64*)(vbase + 2 * p), acc2);
                }
                float2 f = unpk_(acc2);
                sPart[u * 9 + sub] = f.x + f.y;
            }
        }
        __syncthreads();
        if (tid < 60) {
            float s = 0.f;
            #pragma unroll
            for (int k = 0; k < 8; k++) s += sPart[tid * 9 + k];
            g_bmp[bid][tid] = s;
        }
    } else {
        for (int i = (bid - 128) * NTHR + tid; i < MOM_TOTAL; i += 20 * NTHR)
            g_mom[i] = 0.f;
    }
    grid_sync();   // bar1

    // ================= Phase B: blk eval + cross QKV + K-moments. 128 CTAs x 32 tokens =================
    if (bid < 128) {
        float* sWq   = ps;
        float* sBias = ps + 12288;
        float* R     = ps + 12480;
        float* sMomB = R;
        float4* sBQ  = (float4*)(R + 976);

        for (int i = tid; i < 12288; i += NTHR) sWq[i] = Wqkv_c[i];
        if (tid < 192) sBias[tid] = bqkv_c[tid];

        int b  = bid >> 5;
        int t0 = (bid * 32) & 1023;

        {
            const int A_[10] = {0,1,0,2,1,0,3,2,1,0};
            const int B_[10] = {0,0,1,0,1,2,0,1,2,3};
            const float invf[4] = {1.f, 1.f, 0.5f, 1.f/6.f};
            for (int i = tid; i < 960; i += NTHR) {
                int blkI = i / 60, u = i % 60;
                int al = (u % 30) / 3;
                float coef = invf[A_[al]] * invf[B_[al]];
                sMomB[blkI * 61 + u] =
                    (g_bmp[(b*16 + blkI)*2][u] + g_bmp[(b*16 + blkI)*2 + 1][u]) * coef;
            }
        }
        sBQ[tid] = g_bq4[b][t0 + (tid >> 4)][tid & 15];
        __syncthreads();

        {
            int token = tid >> 4, blk = tid & 15;
            float4 q4 = sBQ[tid];
            const float* mom = sMomB + blk * 61;
            float y[4];
            #pragma unroll
            for (int h = 0; h < 2; h++) {
                float q0 = h ? q4.z : q4.x;
                float q1 = h ? q4.w : q4.y;
                float p0[4], p1[4];
                p0[0] = 1.f; p1[0] = 1.f;
                #pragma unroll
                for (int e = 1; e < 4; e++) { p0[e] = p0[e-1] * q0; p1[e] = p1[e-1] * q1; }
                float O0 = 0.f, O1 = 0.f, Z = 0.f;
                int idx = 0;
                #pragma unroll
                for (int n = 0; n <= 3; n++) {
                    #pragma unroll
                    for (int aa = n; aa >= 0; aa--) {
                        float m = p0[aa] * p1[n - aa];
                        const float* r = mom + h * 30 + idx * 3;
                        O0 = fmaf(m, r[0], O0);
                        O1 = fmaf(m, r[1], O1);
                        Z  = fmaf(m, r[2], Z);
                        idx++;
                    }
                }
                float zi = 1.f / Z;
                y[h*2 + 0] = O0 * zi;
                y[h*2 + 1] = O1 * zi;
            }
            const float* W  = Wo_blk + blk * 16;
            const float* bb = bo_blk + blk * 4;
            float4 r;
            r.x = __ldg(&bb[0]) + __ldg(&W[0])*y[0]  + __ldg(&W[1])*y[1]  + __ldg(&W[2])*y[2]  + __ldg(&W[3])*y[3];
            r.y = __ldg(&bb[1]) + __ldg(&W[4])*y[0]  + __ldg(&W[5])*y[1]  + __ldg(&W[6])*y[2]  + __ldg(&W[7])*y[3];
            r.z = __ldg(&bb[2]) + __ldg(&W[8])*y[0]  + __ldg(&W[9])*y[1]  + __ldg(&W[10])*y[2] + __ldg(&W[11])*y[3];
            r.w = __ldg(&bb[3]) + __ldg(&W[12])*y[0] + __ldg(&W[13])*y[1] + __ldg(&W[14])*y[2] + __ldg(&W[15])*y[3];
            *(float4*)&g_ab[b][t0 + token][blk * 4] = r;
        }
        __syncthreads();

        float (*kT)[33] = (float(*)[33])R;
        float (*vT)[33] = (float(*)[33])(R + 2112);
        {
            int lane32 = tid & 31;
            int slice  = tid >> 5;
            int t = t0 + lane32;

            u64 x2[32];
            {
                const ulonglong2* xr = (const ulonglong2*)&g_ab[b][t][0];
                #pragma unroll
                for (int i = 0; i < 16; i++) { ulonglong2 v = xr[i]; x2[2*i] = v.x; x2[2*i+1] = v.y; }
            }
            const float qsc = 0.35355339059327373f;
            #pragma unroll
            for (int jj = 0; jj < 12; jj++) {
                int j = slice * 12 + jj;
                const ulonglong2* w4 = (const ulonglong2*)(sWq + j * 64);
                u64 a0 = 0ull, a1 = 0ull;
                #pragma unroll
                for (int d = 0; d < 16; d++) {
                    ulonglong2 w = w4[d];
                    a0 = fma2_(x2[2*d],     w.x, a0);
                    a1 = fma2_(x2[2*d + 1], w.y, a1);
                }
                float2 fa = unpk_(a0), fb = unpk_(a1);
                float val = (fa.x + fa.y) + (fb.x + fb.y) + sBias[j];
                if (j < 64) {
                    g_cq[b][j >> 3][t][j & 7] = val * qsc;
                } else if (j < 128) {
                    int c = j - 64;
                    g_ck[b][c >> 3][t][c & 7] = val;
                    kT[c][lane32] = val;
                } else {
                    vT[j - 128][lane32] = val;
                }
            }
        }
        __syncthreads();

        if (tid < 360) {
            int h = tid / 45, al = tid % 45;
            int deg, i0, j0; float coef;
            cross_alpha2(al, deg, i0, j0, coef);
            float acc[9];
            #pragma unroll
            for (int g = 0; g < 9; g++) acc[g] = 0.f;
            #pragma unroll 4
            for (int k = 0; k < 32; k++) {
                float m = 1.f;
                if (deg >= 1) m = kT[h*8 + i0][k];
                if (deg >= 2) m *= kT[h*8 + j0][k];
                #pragma unroll
                for (int d = 0; d < 8; d++)
                    acc[d] = fmaf(m, vT[h*8 + d][k], acc[d]);
                acc[8] += m;
            }
            float* dst = &g_mom[CM_OFF + (b*8 + h)*540 + al * 12];
            #pragma unroll
            for (int g = 0; g < 9; g++) atomicAdd(dst + g, acc[g] * coef);
        }
    }
    grid_sync();   // bar2

    // ================= Phase C: cross eval + Q-moments. 1024 items, 8 groups x 64 =================
    if (bid < 128) {
        int g = tid >> 6, gt = tid & 63;
        float* base_ = ps + g * 836;
        float* sM = base_;
        float (*sQT)[33] = (float(*)[33])(base_ + 540);
        float* sZ = base_ + 804;
        int item = bid * 8 + g;
        int qc = item & 31, h = (item >> 5) & 7, b = item >> 8;

        for (int i = gt; i < 135; i += 64)
            ((float4*)sM)[i] = ((const float4*)&g_mom[CM_OFF + (b*8 + h)*540])[i];

        int t = qc * 32 + (gt & 31);
        float q[8];
        if (gt < 32) {
            const float4* qp = (const float4*)&g_cq[b][h][t][0];
            float4 a = qp[0], c = qp[1];
            q[0]=a.x; q[1]=a.y; q[2]=a.z; q[3]=a.w; q[4]=c.x; q[5]=c.y; q[6]=c.z; q[7]=c.w;
            #pragma unroll
            for (int i = 0; i < 8; i++) sQT[i][gt] = q[i];
        }
        GBAR(1 + g, 64);

        if (gt < 32) {
            float a0=0,a1=0,a2=0,a3=0,a4=0,a5=0,a6=0,a7=0,a8=0;
            int idx = 0;
#define FMA9(MV) { float m_ = (MV); const float4* r_ = (const float4*)(sM + idx * 12); \
    float4 ra = r_[0], rb = r_[1], rc = r_[2]; \
    a0 = fmaf(m_, ra.x, a0); a1 = fmaf(m_, ra.y, a1); a2 = fmaf(m_, ra.z, a2); a3 = fmaf(m_, ra.w, a3); \
    a4 = fmaf(m_, rb.x, a4); a5 = fmaf(m_, rb.y, a5); a6 = fmaf(m_, rb.z, a6); a7 = fmaf(m_, rb.w, a7); \
    a8 = fmaf(m_, rc.x, a8); idx++; }
            FMA9(1.f);
            #pragma unroll
            for (int i = 0; i < 8; i++) FMA9(q[i]);
            #pragma unroll
            for (int i = 0; i < 8; i++) {
                #pragma unroll
                for (int j = i; j < 8; j++) FMA9(q[i] * q[j]);
            }
#undef FMA9
            float zi = 1.f / a8;
            float4* dst = (float4*)&g_ao[b][t][h * 8];
            dst[0] = make_float4(a0*zi, a1*zi, a2*zi, a3*zi);
            dst[1] = make_float4(a4*zi, a5*zi, a6*zi, a7*zi);
            sZ[gt] = zi;
        }
        GBAR(1 + g, 64);

        if (gt < 45) {
            int deg, i0, j0; float coef;
            cross_alpha2(gt, deg, i0, j0, coef);
            float acc = 0.f;
            #pragma unroll 4
            for (int k = 0; k < 32; k++) {
                float m = sZ[k];
                if (deg >= 1) m *= sQT[i0][k];
                if (deg >= 2) m *= sQT[j0][k];
                acc += m;
            }
            atomicAdd(&g_mom[CN_OFF + (b*8 + h)*45 + gt], acc * coef);
        }
    }
    grid_sync();   // bar3

    // ================= Phase D: epilogue + fused recv. 128 CTAs, 8 warps x 4 tokens =================
    if (bid < 128) {
        int bblk = bid >> 5;
        for (int i = tid; i < 360; i += NTHR)
            sN[i] = g_mom[CN_OFF + bblk * 360 + i];
        __syncthreads();

        int w = tid >> 5, lane = tid & 31;
        if (w < 8) {
            float* base_ = ps + w * 1792;
            float* ao4 = base_;
            float* y4  = base_ + 256;
            float* gh4 = base_ + 512;
            float* z4  = base_ + 1536;
            int b = (bid * 32) >> 10;
            int t0 = (bid * 32 + w * 4) & 1023;

            #pragma unroll
            for (int j = 0; j < 4; j++) {
                const float* aor = &g_ao[b][t0 + j][0];
                ao4[lane * 4 + j]        = aor[lane];
                ao4[(lane + 32) * 4 + j] = aor[lane + 32];
            }
            __syncwarp();

            u64 co2[4];
            #pragma unroll
            for (int j = 0; j < 4; j++) co2[j] = pk_(sboc[lane], sboc[lane + 32]);
            #pragma unroll 2
            for (int jj = 0; jj < 64; jj++) {
                u64 ww = *(const u64*)(sWoP + jj * 64 + ((lane * 2) ^ ((jj & 31) * 2)));
                float4 a4 = *(const float4*)(ao4 + jj * 4);
                co2[0] = fma2_(pk_(a4.x, a4.x), ww, co2[0]);
                co2[1] = fma2_(pk_(a4.y, a4.y), ww, co2[1]);
                co2[2] = fma2_(pk_(a4.z, a4.z), ww, co2[2]);
                co2[3] = fma2_(pk_(a4.w, a4.w), ww, co2[3]);
            }

            float y0v[4], y1v[4];
            #pragma unroll
            for (int j = 0; j < 4; j++) {
                float2 co = unpk_(co2[j]);
                float x0 = g_ab[b][t0 + j][lane] + co.x;
                float x1 = g_ab[b][t0 + j][lane + 32] + co.y;
                float mean = wsum(x0 + x1) * (1.0f / 64.0f);
                float d0 = x0 - mean, d1 = x1 - mean;
                float var = wsum(d0 * d0 + d1 * d1) * (1.0f / 64.0f);
                float inv = rsqrtf(var + 1e-5f);
                y0v[j] = d0 * inv * sg1[lane] + sbe1[lane];
                y1v[j] = d1 * inv * sg1[lane + 32] + sbe1[lane + 32];
                y4[lane * 4 + j]        = y0v[j];
                y4[(lane + 32) * 4 + j] = y1v[j];
            }
            __syncwarp();

            #pragma unroll
            for (int mh = 0; mh < 2; mh++) {
                u64 acc2[4][2];
                #pragma unroll
                for (int j = 0; j < 4; j++)
                    #pragma unroll
                    for (int m = 0; m < 2; m++)
                        acc2[j][m] = pk_(sb1[lane + (mh*2+m)*64], sb1[lane + (mh*2+m)*64 + 32]);
                #pragma unroll 2
                for (int d = 0; d < 64; d++) {
                    const float* row = sW1P + d * 256;
                    int sw = (d & 31) * 2;
                    u64 wv0 = *(const u64*)(row + ((mh*2+0) * 64 + ((lane * 2) ^ sw)));
                    u64 wv1 = *(const u64*)(row + ((mh*2+1) * 64 + ((lane * 2) ^ sw)));
                    float4 yd4 = *(const float4*)(y4 + d * 4);
                    u64 yp[4] = {pk_(yd4.x, yd4.x), pk_(yd4.y, yd4.y), pk_(yd4.z, yd4.z), pk_(yd4.w, yd4.w)};
                    #pragma unroll
                    for (int j = 0; j < 4; j++) {
                        acc2[j][0] = fma2_(yp[j], wv0, acc2[j][0]);
                        acc2[j][1] = fma2_(yp[j], wv1, acc2[j][1]);
                    }
                }
                #pragma unroll
                for (int j = 0; j < 4; j++) {
                    #pragma unroll
                    for (int m = 0; m < 2; m++) {
                        float2 f = unpk_(acc2[j][m]);
                        gh4[(lane + (mh*2+m)*64) * 4 + j]      = gelu_(f.x);
                        gh4[(lane + (mh*2+m)*64 + 32) * 4 + j] = gelu_(f.y);
                    }
                }
            }
            __syncwarp();

            u64 f2[4];
            #pragma unroll
            for (int j = 0; j < 4; j++) f2[j] = pk_(sb2[lane], sb2[lane + 32]);
            #pragma unroll 2
            for (int jj = 0; jj < 256; jj++) {
                u64 ww = *(const u64*)(sW2P + jj * 64 + ((lane * 2) ^ ((jj & 31) * 2)));
                float4 g4 = *(const float4*)(gh4 + jj * 4);
                f2[0] = fma2_(pk_(g4.x, g4.x), ww, f2[0]);
                f2[1] = fma2_(pk_(g4.y, g4.y), ww, f2[1]);
                f2[2] = fma2_(pk_(g4.z, g4.z), ww, f2[2]);
                f2[3] = fma2_(pk_(g4.w, g4.w), ww, f2[3]);
            }

            #pragma unroll
            for (int j = 0; j < 4; j++) {
                int t = t0 + j;
                float2 ff = unpk_(f2[j]);
                float u0 = y0v[j] + ff.x, u1 = y1v[j] + ff.y;
                float m2 = wsum(u0 + u1) * (1.0f / 64.0f);
                float e0 = u0 - m2, e1 = u1 - m2;
                float v2 = wsum(e0 * e0 + e1 * e1) * (1.0f / 64.0f);
                float iv2 = rsqrtf(v2 + 1e-5f);
                z4[lane * 4 + j]        = e0 * iv2 * sg2[lane] + sbe2[lane];
                z4[(lane + 32) * 4 + j] = e1 * iv2 * sg2[lane + 32] + sbe2[lane + 32];

                float rpart = 0.f;
                if (lane < 8) {
                    int hh = lane;
                    const float4* kp = (const float4*)&g_ck[b][hh][t][0];
                    float4 ka = kp[0], kb = kp[1];
                    float k[8] = {ka.x, ka.y, ka.z, ka.w, kb.x, kb.y, kb.z, kb.w};
                    const float* N = sN + hh * 45;
                    float acc = N[0];
                    int idx = 1;
                    #pragma unroll
                    for (int i = 0; i < 8; i++) acc = fmaf(k[i], N[idx++], acc);
                    #pragma unroll
                    for (int i = 0; i < 8; i++) {
                        #pragma unroll
                        for (int jq = i; jq < 8; jq++) acc = fmaf(k[i] * k[jq], N[idx++], acc);
                    }
                    rpart = acc;
                }
                float recv_tot = wsum(rpart);
                __syncwarp();

                if (lane < 16) {
                    int i = lane, rb = i >> 2, cb = i & 3;
                    int tk = tok[b * 1024 + t];
                    float recv = recv_tot * (1.0f / 8192.0f);
                    float sv = semb[(size_t)tk * 16 + i] + recv * salp[i];
                    float sg = 1.0f / (1.0f + expf(-sv));
                    const float* Mr = M + ((size_t)(b * 1024 + t)) * 64;
                    float* Or = out + ((size_t)(b * 1024 + t)) * 64;
                    int base = 16 * rb + 2 * cb;
                    #pragma unroll
                    for (int e = 0; e < 4; e++) {
                        int r = e >> 1, c = e & 1;
                        int mi = base + 8 * r + c;
                        float bv = Mr[mi];
                        Or[mi] = bv + (z4[(i * 4 + e) * 4 + j] - bv) * sg;
                    }
                }
                __syncwarp();
            }
        }
    }
}

// ---------------- launch ----------------
extern "C" void kernel_launch(void* const* d_in, const int* in_sizes, int n_in,
                              void* d_out, int out_size)
{
    const float* M        = (const float*)d_in[0];
    const int*   tok      = (const int*)d_in[1];
    const float* Wqkv_blk = (const float*)d_in[2];
    const float* bqkv_blk = (const float*)d_in[3];
    const float* Wo_blk   = (const float*)d_in[4];
    const float* bo_blk   = (const float*)d_in[5];
    const float* Wqkv_c   = (const float*)d_in[6];
    const float* bqkv_c   = (const float*)d_in[7];
    const float* Wo_c     = (const float*)d_in[8];
    const float* bo_c     = (const float*)d_in[9];
    const float* W1       = (const float*)d_in[10];
    const float* b1       = (const float*)d_in[11];
    const float* W2       = (const float*)d_in[12];
    const float* b2       = (const float*)d_in[13];
    const float* g1       = (const float*)d_in[14];
    const float* be1      = (const float*)d_in[15];
    const float* g2       = (const float*)d_in[16];
    const float* be2      = (const float*)d_in[17];
    const float* semb     = (const float*)d_in[18];
    const float* alpha    = (const float*)d_in[19];
    float* out = (float*)d_out;

    static bool init_done = false;
    if (!init_done) {
        cudaFuncSetAttribute(k_all, cudaFuncAttributeMaxDynamicSharedMemorySize, SMEM_BYTES);
        init_done = true;
    }

    k_all<<<GRID, NTHR, SMEM_BYTES>>>(M, tok, Wqkv_blk, bqkv_blk, Wo_blk, bo_blk,
                                      Wqkv_c, bqkv_c, Wo_c, bo_c, W1, b1, W2, b2,
                                      g1, be1, g2, be2, semb, alpha, out);
}

// round 17
// speedup vs baseline: 1.2301x; 1.0005x over previous
#include <cuda_runtime.h>

#define TB 1024
#define NB 4
#define GRID 148
#define NTHR 512

typedef unsigned long long u64;

// ---------------- global scratch ----------------
#define CM_OFF 0
#define CN_OFF 17280
#define MOM_TOTAL 18720
__device__ float  g_mom[MOM_TOTAL];
__device__ float  g_bmp[128][60];
__device__ float4 g_bq4[NB][TB][16];
__device__ float  g_ab[NB][TB][64];
__device__ float  g_cq[NB][8][TB][8];
__device__ float  g_ck[NB][8][TB][8];
__device__ float  g_ao[NB][TB][64];

__device__ unsigned g_bar_cnt = 0;
__device__ unsigned g_bar_gen = 0;

__device__ __forceinline__ void grid_sync() {
    __syncthreads();
    if (threadIdx.x == 0) {
        unsigned gen;
        asm volatile("ld.global.acquire.gpu.u32 %0, [%1];" : "=r"(gen) : "l"(&g_bar_gen));
        __threadfence();
        unsigned prev;
        asm volatile("atom.global.release.gpu.add.u32 %0, [%1], %2;"
                     : "=r"(prev) : "l"(&g_bar_cnt), "r"(1u) : "memory");
        if (prev == GRID - 1) {
            asm volatile("st.global.relaxed.gpu.u32 [%0], %1;" :: "l"(&g_bar_cnt), "r"(0u) : "memory");
            asm volatile("st.global.release.gpu.u32 [%0], %1;" :: "l"(&g_bar_gen), "r"(gen + 1u) : "memory");
        } else {
            unsigned cur;
            do {
                asm volatile("ld.global.acquire.gpu.u32 %0, [%1];" : "=r"(cur) : "l"(&g_bar_gen));
            } while (cur == gen);
        }
    }
    __syncthreads();
}

#define GBAR(id, cnt) asm volatile("bar.sync %0, %1;" :: "r"(id), "r"(cnt) : "memory")

__device__ __forceinline__ u64 fma2_(u64 a, u64 b, u64 c) {
    u64 r; asm("fma.rn.f32x2 %0, %1, %2, %3;" : "=l"(r) : "l"(a), "l"(b), "l"(c)); return r;
}
__device__ __forceinline__ u64 mul2_(u64 a, u64 b) {
    u64 r; asm("mul.rn.f32x2 %0, %1, %2;" : "=l"(r) : "l"(a), "l"(b)); return r;
}
__device__ __forceinline__ u64 add2_(u64 a, u64 b) {
    u64 r; asm("add.rn.f32x2 %0, %1, %2;" : "=l"(r) : "l"(a), "l"(b)); return r;
}
__device__ __forceinline__ float2 unpk_(u64 v) {
    float2 r; asm("mov.b64 {%0, %1}, %2;" : "=f"(r.x), "=f"(r.y) : "l"(v)); return r;
}
__device__ __forceinline__ u64 pk_(float lo, float hi) {
    u64 r; asm("mov.b64 %0, {%1, %2};" : "=l"(r) : "f"(lo), "f"(hi)); return r;
}
__device__ __forceinline__ float wsum(float v) {
    #pragma unroll
    for (int o = 16; o > 0; o >>= 1) v += __shfl_xor_sync(0xffffffffu, v, o);
    return v;
}
__device__ __forceinline__ float gelu_(float x) {
    return 0.5f * x * (1.0f + erff(x * 0.7071067811865476f));
}
__device__ __forceinline__ void cross_alpha2(int alpha, int& deg, int& i0, int& j0, float& coef) {
    deg = 0; i0 = 0; j0 = 0; coef = 1.f;
    if (alpha == 0) { deg = 0; }
    else if (alpha < 9) { deg = 1; i0 = alpha - 1; }
    else {
        deg = 2; int r = alpha - 9; int ii = 0;
        while (r >= 8 - ii) { r -= 8 - ii; ii++; }
        i0 = ii; j0 = ii + r;
        coef = (i0 == j0) ? 0.5f : 1.f;
    }
}

#define PS_OFF 37880
#define SCRATCH_FLOATS 18156
#define SMEM_FLOATS (PS_OFF + SCRATCH_FLOATS)
#define SMEM_BYTES (SMEM_FLOATS * 4)

#define KPS 522
#define WQ_OFF 5676    // Wqkv_c staging inside ps (disjoint from A scratch)

__global__ void __launch_bounds__(NTHR, 1)
k_all(const float* __restrict__ M,
      const int* __restrict__ tok,
      const float* __restrict__ Wqkv_blk, const float* __restrict__ bqkv_blk,
      const float* __restrict__ Wo_blk,   const float* __restrict__ bo_blk,
      const float* __restrict__ Wqkv_c,   const float* __restrict__ bqkv_c,
      const float* __restrict__ Woc,      const float* __restrict__ boc,
      const float* __restrict__ W1,       const float* __restrict__ b1,
      const float* __restrict__ W2,       const float* __restrict__ b2,
      const float* __restrict__ g1,       const float* __restrict__ be1,
      const float* __restrict__ g2,       const float* __restrict__ be2,
      const float* __restrict__ semb,     const float* __restrict__ alpha,
      float* __restrict__ out)
{
    extern __shared__ float sm[];
    const int tid = threadIdx.x;
    const int bid = blockIdx.x;

    float* sWoP = sm;
    float* sW1P = sm + 4096;
    float* sW2P = sm + 20480;
    float* sSm  = sm + 36864;
    float* sboc = sSm;        float* sb1  = sSm + 64;  float* sb2  = sSm + 320;
    float* sg1  = sSm + 384;  float* sbe1 = sSm + 448; float* sg2  = sSm + 512;
    float* sbe2 = sSm + 576;  float* salp = sSm + 640;
    float* sN = sm + 37520;
    float* ps = sm + PS_OFF;

    // ---------- prologue: small arrays only ----------
    for (int i = tid; i < 64; i += NTHR) { sboc[i] = boc[i]; sb2[i] = b2[i];
                                           sg1[i] = g1[i]; sbe1[i] = be1[i];
                                           sg2[i] = g2[i]; sbe2[i] = be2[i]; }
    if (tid < 256) sb1[tid] = b1[tid];
    if (tid < 16) salp[tid] = alpha[tid];

    // ================= Phase A: blk QKV + partial moments. 128 CTAs =================
    if (bid < 128) {
        int b = bid >> 5, blk = (bid >> 1) & 15, half = bid & 1;
        float* sW  = ps;
        float* sB  = ps + 768;
        float* sKP = ps + 960;
        float* sPart = ps + 960 + 8 * KPS;

        for (int i = tid; i < 768; i += NTHR) sW[i] = Wqkv_blk[i];
        if (tid < 192) sB[tid] = bqkv_blk[tid];
        __syncthreads();

        int rb = blk >> 2, cb = blk & 3;
        int basec = 16 * rb + 2 * cb;
        const float* W  = sW + blk * 48;
        const float* bb = sB + blk * 12;
        const float qs = 0.70710678118654752f;

        int t = half * 512 + tid;
        {
            const float* Mr = M + ((size_t)(b * 1024 + t)) * 64;
            float2 xa = *(const float2*)(Mr + basec);
            float2 xb = *(const float2*)(Mr + basec + 8);
            float x0 = xa.x, x1 = xa.y, x2 = xb.x, x3 = xb.y;
            float o[12];
            #pragma unroll
            for (int j = 0; j < 12; j++)
                o[j] = fmaf(W[j*4], x0, fmaf(W[j*4+1], x1, fmaf(W[j*4+2], x2, fmaf(W[j*4+3], x3, bb[j]))));
            g_bq4[b][t][blk] = make_float4(o[0]*qs, o[1]*qs, o[2]*qs, o[3]*qs);
            #pragma unroll
            for (int c = 0; c < 4; c++) {
                sKP[c * KPS + tid]       = o[4 + c];
                sKP[(4 + c) * KPS + tid] = o[8 + c];
            }
        }
        __syncthreads();

        {
            int sub = tid >> 6, u = tid & 63;
            if (u < 60) {
                int h = u / 30, rem = u % 30, al = rem / 3, g = rem % 3;
                const int A_[10] = {0,1,0,2,1,0,3,2,1,0};
                const int B_[10] = {0,0,1,0,1,2,0,1,2,3};
                int a = A_[al], be = B_[al], ab = a + be;
                const float* k0base = sKP + (2*h) * KPS;
                const float* k1base = sKP + (2*h + 1) * KPS;
                const float* vbase  = (g < 2) ? (sKP + (4 + 2*h + g) * KPS) : k0base;
                const u64 ONE2 = pk_(1.f, 1.f);
                u64 acc2 = 0ull;
                int p0 = sub * 32;
                #pragma unroll 4
                for (int p = p0; p < p0 + 32; p++) {
                    u64 K0 = *(const u64*)(k0base + 2 * p);
                    u64 K1 = *(const u64*)(k1base + 2 * p);
                    u64 f0 = (0 < a) ? K0 : ((0 < ab) ? K1 : ONE2);
                    u64 f1 = (1 < a) ? K0 : ((1 < ab) ? K1 : ONE2);
                    u64 f2 = (2 < a) ? K0 : ((2 < ab) ? K1 : ONE2);
                    u64 m2 = mul2_(mul2_(f0, f1), f2);
                    if (g == 2) acc2 = add2_(acc2, m2);
                    else        acc2 = fma2_(m2, *(const u64*)(vbase + 2 * p), acc2);
                }
                float2 f = unpk_(acc2);
                sPart[u * 9 + sub] = f.x + f.y;
            }
        }
        __syncthreads();
        if (tid < 60) {
            float s = 0.f;
            #pragma unroll
            for (int k = 0; k < 8; k++) s += sPart[tid * 9 + k];
            g_bmp[bid][tid] = s;
        }
        // stage Wqkv_c for Phase B (disjoint smem; drains during bar1 wait)
        for (int i = tid; i < 12288; i += NTHR) ps[WQ_OFF + i] = Wqkv_c[i];
        if (tid < 192) ps[WQ_OFF + 12288 + tid] = bqkv_c[tid];
    } else {
        for (int i = (bid - 128) * NTHR + tid; i < MOM_TOTAL; i += 20 * NTHR)
            g_mom[i] = 0.f;
    }
    grid_sync();   // bar1

    // ================= Phase B: blk eval + cross QKV + K-moments. 128 CTAs x 32 tokens =================
    if (bid < 128) {
        float* sWq   = ps + WQ_OFF;           // staged in Phase A
        float* sBias = ps + WQ_OFF + 12288;
        float* R     = ps;                    // [0, 4224) — A scratch is dead
        float* sMomB = R;
        float4* sBQ  = (float4*)(R + 976);

        int b  = bid >> 5;
        int t0 = (bid * 32) & 1023;

        {
            const int A_[10] = {0,1,0,2,1,0,3,2,1,0};
            const int B_[10] = {0,0,1,0,1,2,0,1,2,3};
            const float invf[4] = {1.f, 1.f, 0.5f, 1.f/6.f};
            for (int i = tid; i < 960; i += NTHR) {
                int blkI = i / 60, u = i % 60;
                int al = (u % 30) / 3;
                float coef = invf[A_[al]] * invf[B_[al]];
                sMomB[blkI * 61 + u] =
                    (g_bmp[(b*16 + blkI)*2][u] + g_bmp[(b*16 + blkI)*2 + 1][u]) * coef;
            }
        }
        sBQ[tid] = g_bq4[b][t0 + (tid >> 4)][tid & 15];
        __syncthreads();

        {
            int token = tid >> 4, blk = tid & 15;
            float4 q4 = sBQ[tid];
            const float* mom = sMomB + blk * 61;
            float y[4];
            #pragma unroll
            for (int h = 0; h < 2; h++) {
                float q0 = h ? q4.z : q4.x;
                float q1 = h ? q4.w : q4.y;
                float p0[4], p1[4];
                p0[0] = 1.f; p1[0] = 1.f;
                #pragma unroll
                for (int e = 1; e < 4; e++) { p0[e] = p0[e-1] * q0; p1[e] = p1[e-1] * q1; }
                float O0 = 0.f, O1 = 0.f, Z = 0.f;
                int idx = 0;
                #pragma unroll
                for (int n = 0; n <= 3; n++) {
                    #pragma unroll
                    for (int aa = n; aa >= 0; aa--) {
                        float m = p0[aa] * p1[n - aa];
                        const float* r = mom + h * 30 + idx * 3;
                        O0 = fmaf(m, r[0], O0);
                        O1 = fmaf(m, r[1], O1);
                        Z  = fmaf(m, r[2], Z);
                        idx++;
                    }
                }
                float zi = 1.f / Z;
                y[h*2 + 0] = O0 * zi;
                y[h*2 + 1] = O1 * zi;
            }
            const float* W  = Wo_blk + blk * 16;
            const float* bb = bo_blk + blk * 4;
            float4 r;
            r.x = __ldg(&bb[0]) + __ldg(&W[0])*y[0]  + __ldg(&W[1])*y[1]  + __ldg(&W[2])*y[2]  + __ldg(&W[3])*y[3];
            r.y = __ldg(&bb[1]) + __ldg(&W[4])*y[0]  + __ldg(&W[5])*y[1]  + __ldg(&W[6])*y[2]  + __ldg(&W[7])*y[3];
            r.z = __ldg(&bb[2]) + __ldg(&W[8])*y[0]  + __ldg(&W[9])*y[1]  + __ldg(&W[10])*y[2] + __ldg(&W[11])*y[3];
            r.w = __ldg(&bb[3]) + __ldg(&W[12])*y[0] + __ldg(&W[13])*y[1] + __ldg(&W[14])*y[2] + __ldg(&W[15])*y[3];
            *(float4*)&g_ab[b][t0 + token][blk * 4] = r;
        }
        __syncthreads();

        float (*kT)[33] = (float(*)[33])R;
        float (*vT)[33] = (float(*)[33])(R + 2112);
        {
            int lane32 = tid & 31;
            int slice  = tid >> 5;
            int t = t0 + lane32;

            u64 x2[32];
            {
                const ulonglong2* xr = (const ulonglong2*)&g_ab[b][t][0];
                #pragma unroll
                for (int i = 0; i < 16; i++) { ulonglong2 v = xr[i]; x2[2*i] = v.x; x2[2*i+1] = v.y; }
            }
            const float qsc = 0.35355339059327373f;
            #pragma unroll
            for (int jj = 0; jj < 12; jj++) {
                int j = slice * 12 + jj;
                const ulonglong2* w4 = (const ulonglong2*)(sWq + j * 64);
                u64 a0 = 0ull, a1 = 0ull;
                #pragma unroll
                for (int d = 0; d < 16; d++) {
                    ulonglong2 w = w4[d];
                    a0 = fma2_(x2[2*d],     w.x, a0);
                    a1 = fma2_(x2[2*d + 1], w.y, a1);
                }
                float2 fa = unpk_(a0), fb = unpk_(a1);
                float val = (fa.x + fa.y) + (fb.x + fb.y) + sBias[j];
                if (j < 64) {
                    g_cq[b][j >> 3][t][j & 7] = val * qsc;
                } else if (j < 128) {
                    int c = j - 64;
                    g_ck[b][c >> 3][t][c & 7] = val;
                    kT[c][lane32] = val;
                } else {
                    vT[j - 128][lane32] = val;
                }
            }
        }
        __syncthreads();

        if (tid < 360) {
            int h = tid / 45, al = tid % 45;
            int deg, i0, j0; float coef;
            cross_alpha2(al, deg, i0, j0, coef);
            float acc[9];
            #pragma unroll
            for (int g = 0; g < 9; g++) acc[g] = 0.f;
            #pragma unroll 4
            for (int k = 0; k < 32; k++) {
                float m = 1.f;
                if (deg >= 1) m = kT[h*8 + i0][k];
                if (deg >= 2) m *= kT[h*8 + j0][k];
                #pragma unroll
                for (int d = 0; d < 8; d++)
                    acc[d] = fmaf(m, vT[h*8 + d][k], acc[d]);
                acc[8] += m;
            }
            float* dst = &g_mom[CM_OFF + (b*8 + h)*540 + al * 12];
            #pragma unroll
            for (int g = 0; g < 9; g++) atomicAdd(dst + g, acc[g] * coef);
        }
    }
    grid_sync();   // bar2

    // ================= Phase C: cross eval + Q-moments + epilogue weight staging =================
    if (bid < 128) {
        int g = tid >> 6, gt = tid & 63;
        float* base_ = ps + g * 836;
        float* sM = base_;
        float (*sQT)[33] = (float(*)[33])(base_ + 540);
        float* sZ = base_ + 804;
        int item = bid * 8 + g;
        int qc = item & 31, h = (item >> 5) & 7, b = item >> 8;

        for (int i = gt; i < 135; i += 64)
            ((float4*)sM)[i] = ((const float4*)&g_mom[CM_OFF + (b*8 + h)*540])[i];

        int t = qc * 32 + (gt & 31);
        float q[8];
        if (gt < 32) {
            const float4* qp = (const float4*)&g_cq[b][h][t][0];
            float4 a = qp[0], c = qp[1];
            q[0]=a.x; q[1]=a.y; q[2]=a.z; q[3]=a.w; q[4]=c.x; q[5]=c.y; q[6]=c.z; q[7]=c.w;
            #pragma unroll
            for (int i = 0; i < 8; i++) sQT[i][gt] = q[i];
        }
        GBAR(1 + g, 64);

        if (gt < 32) {
            float a0=0,a1=0,a2=0,a3=0,a4=0,a5=0,a6=0,a7=0,a8=0;
            int idx = 0;
#define FMA9(MV) { float m_ = (MV); const float4* r_ = (const float4*)(sM + idx * 12); \
    float4 ra = r_[0], rb = r_[1], rc = r_[2]; \
    a0 = fmaf(m_, ra.x, a0); a1 = fmaf(m_, ra.y, a1); a2 = fmaf(m_, ra.z, a2); a3 = fmaf(m_, ra.w, a3); \
    a4 = fmaf(m_, rb.x, a4); a5 = fmaf(m_, rb.y, a5); a6 = fmaf(m_, rb.z, a6); a7 = fmaf(m_, rb.w, a7); \
    a8 = fmaf(m_, rc.x, a8); idx++; }
            FMA9(1.f);
            #pragma unroll
            for (int i = 0; i < 8; i++) FMA9(q[i]);
            #pragma unroll
            for (int i = 0; i < 8; i++) {
                #pragma unroll
                for (int j = i; j < 8; j++) FMA9(q[i] * q[j]);
            }
#undef FMA9
            float zi = 1.f / a8;
            float4* dst = (float4*)&g_ao[b][t][h * 8];
            dst[0] = make_float4(a0*zi, a1*zi, a2*zi, a3*zi);
            dst[1] = make_float4(a4*zi, a5*zi, a6*zi, a7*zi);
            sZ[gt] = zi;
        }
        GBAR(1 + g, 64);

        if (gt < 45) {
            int deg, i0, j0; float coef;
            cross_alpha2(gt, deg, i0, j0, coef);
            float acc = 0.f;
            #pragma unroll 4
            for (int k = 0; k < 32; k++) {
                float m = sZ[k];
                if (deg >= 1) m *= sQT[i0][k];
                if (deg >= 2) m *= sQT[j0][k];
                acc += m;
            }
            atomicAdd(&g_mom[CN_OFF + (b*8 + h)*45 + gt], acc * coef);
        }

        // stage epilogue weights (swizzled); drains during bar3 wait
        for (int i = tid; i < 4096; i += NTHR) {
            int d = i >> 6, j = i & 63;
            int pos = ((d & 31) * 2 + (d >> 5)) ^ ((j & 31) * 2);
            sWoP[j * 64 + pos] = Woc[i];
        }
        for (int i = tid; i < 16384; i += NTHR) {
            int j = i >> 6, d = i & 63;
            int q2 = ((j >> 6) * 32 + (j & 31)) * 2 + ((j >> 5) & 1);
            sW1P[d * 256 + (q2 ^ ((d & 31) * 2))] = W1[i];
        }
        for (int i = tid; i < 16384; i += NTHR) {
            int d = i >> 8, j = i & 255;
            int pos = ((d & 31) * 2 + (d >> 5)) ^ ((j & 31) * 2);
            sW2P[j * 64 + pos] = W2[i];
        }
    }
    grid_sync();   // bar3

    // ================= Phase D: epilogue + fused recv. 128 CTAs, 8 warps x 4 tokens =================
    if (bid < 128) {
        int bblk = bid >> 5;
        for (int i = tid; i < 360; i += NTHR)
            sN[i] = g_mom[CN_OFF + bblk * 360 + i];
        __syncthreads();

        int w = tid >> 5, lane = tid & 31;
        if (w < 8) {
            float* base_ = ps + w * 1792;
            float* ao4 = base_;
            float* y4  = base_ + 256;
            float* gh4 = base_ + 512;
            float* z4  = base_ + 1536;
            int b = (bid * 32) >> 10;
            int t0 = (bid * 32 + w * 4) & 1023;

            #pragma unroll
            for (int j = 0; j < 4; j++) {
                const float* aor = &g_ao[b][t0 + j][0];
                ao4[lane * 4 + j]        = aor[lane];
                ao4[(lane + 32) * 4 + j] = aor[lane + 32];
            }
            __syncwarp();

            u64 co2[4];
            #pragma unroll
            for (int j = 0; j < 4; j++) co2[j] = pk_(sboc[lane], sboc[lane + 32]);
            #pragma unroll 2
            for (int jj = 0; jj < 64; jj++) {
                u64 ww = *(const u64*)(sWoP + jj * 64 + ((lane * 2) ^ ((jj & 31) * 2)));
                float4 a4 = *(const float4*)(ao4 + jj * 4);
                co2[0] = fma2_(pk_(a4.x, a4.x), ww, co2[0]);
                co2[1] = fma2_(pk_(a4.y, a4.y), ww, co2[1]);
                co2[2] = fma2_(pk_(a4.z, a4.z), ww, co2[2]);
                co2[3] = fma2_(pk_(a4.w, a4.w), ww, co2[3]);
            }

            float y0v[4], y1v[4];
            #pragma unroll
            for (int j = 0; j < 4; j++) {
                float2 co = unpk_(co2[j]);
                float x0 = g_ab[b][t0 + j][lane] + co.x;
                float x1 = g_ab[b][t0 + j][lane + 32] + co.y;
                float mean = wsum(x0 + x1) * (1.0f / 64.0f);
                float d0 = x0 - mean, d1 = x1 - mean;
                float var = wsum(d0 * d0 + d1 * d1) * (1.0f / 64.0f);
                float inv = rsqrtf(var + 1e-5f);
                y0v[j] = d0 * inv * sg1[lane] + sbe1[lane];
                y1v[j] = d1 * inv * sg1[lane + 32] + sbe1[lane + 32];
                y4[lane * 4 + j]        = y0v[j];
                y4[(lane + 32) * 4 + j] = y1v[j];
            }
            __syncwarp();

            #pragma unroll
            for (int mh = 0; mh < 2; mh++) {
                u64 acc2[4][2];
                #pragma unroll
                for (int j = 0; j < 4; j++)
                    #pragma unroll
                    for (int m = 0; m < 2; m++)
                        acc2[j][m] = pk_(sb1[lane + (mh*2+m)*64], sb1[lane + (mh*2+m)*64 + 32]);
                #pragma unroll 2
                for (int d = 0; d < 64; d++) {
                    const float* row = sW1P + d * 256;
                    int sw = (d & 31) * 2;
                    u64 wv0 = *(const u64*)(row + ((mh*2+0) * 64 + ((lane * 2) ^ sw)));
                    u64 wv1 = *(const u64*)(row + ((mh*2+1) * 64 + ((lane * 2) ^ sw)));
                    float4 yd4 = *(const float4*)(y4 + d * 4);
                    u64 yp[4] = {pk_(yd4.x, yd4.x), pk_(yd4.y, yd4.y), pk_(yd4.z, yd4.z), pk_(yd4.w, yd4.w)};
                    #pragma unroll
                    for (int j = 0; j < 4; j++) {
                        acc2[j][0] = fma2_(yp[j], wv0, acc2[j][0]);
                        acc2[j][1] = fma2_(yp[j], wv1, acc2[j][1]);
                    }
                }
                #pragma unroll
                for (int j = 0; j < 4; j++) {
                    #pragma unroll
                    for (int m = 0; m < 2; m++) {
                        float2 f = unpk_(acc2[j][m]);
                        gh4[(lane + (mh*2+m)*64) * 4 + j]      = gelu_(f.x);
                        gh4[(lane + (mh*2+m)*64 + 32) * 4 + j] = gelu_(f.y);
                    }
                }
            }
            __syncwarp();

            u64 f2[4];
            #pragma unroll
            for (int j = 0; j < 4; j++) f2[j] = pk_(sb2[lane], sb2[lane + 32]);
            #pragma unroll 2
            for (int jj = 0; jj < 256; jj++) {
                u64 ww = *(const u64*)(sW2P + jj * 64 + ((lane * 2) ^ ((jj & 31) * 2)));
                float4 g4 = *(const float4*)(gh4 + jj * 4);
                f2[0] = fma2_(pk_(g4.x, g4.x), ww, f2[0]);
                f2[1] = fma2_(pk_(g4.y, g4.y), ww, f2[1]);
                f2[2] = fma2_(pk_(g4.z, g4.z), ww, f2[2]);
                f2[3] = fma2_(pk_(g4.w, g4.w), ww, f2[3]);
            }

            #pragma unroll
            for (int j = 0; j < 4; j++) {
                int t = t0 + j;
                float2 ff = unpk_(f2[j]);
                float u0 = y0v[j] + ff.x, u1 = y1v[j] + ff.y;
                float m2 = wsum(u0 + u1) * (1.0f / 64.0f);
                float e0 = u0 - m2, e1 = u1 - m2;
                float v2 = wsum(e0 * e0 + e1 * e1) * (1.0f / 64.0f);
                float iv2 = rsqrtf(v2 + 1e-5f);
                z4[lane * 4 + j]        = e0 * iv2 * sg2[lane] + sbe2[lane];
                z4[(lane + 32) * 4 + j] = e1 * iv2 * sg2[lane + 32] + sbe2[lane + 32];

                float rpart = 0.f;
                if (lane < 8) {
                    int hh = lane;
                    const float4* kp = (const float4*)&g_ck[b][hh][t][0];
                    float4 ka = kp[0], kb = kp[1];
                    float k[8] = {ka.x, ka.y, ka.z, ka.w, kb.x, kb.y, kb.z, kb.w};
                    const float* N = sN + hh * 45;
                    float acc = N[0];
                    int idx = 1;
                    #pragma unroll
                    for (int i = 0; i < 8; i++) acc = fmaf(k[i], N[idx++], acc);
                    #pragma unroll
                    for (int i = 0; i < 8; i++) {
                        #pragma unroll
                        for (int jq = i; jq < 8; jq++) acc = fmaf(k[i] * k[jq], N[idx++], acc);
                    }
                    rpart = acc;
                }
                float recv_tot = wsum(rpart);
                __syncwarp();

                if (lane < 16) {
                    int i = lane, rb = i >> 2, cb = i & 3;
                    int tk = tok[b * 1024 + t];
                    float recv = recv_tot * (1.0f / 8192.0f);
                    float sv = semb[(size_t)tk * 16 + i] + recv * salp[i];
                    float sg = 1.0f / (1.0f + expf(-sv));
                    const float* Mr = M + ((size_t)(b * 1024 + t)) * 64;
                    float* Or = out + ((size_t)(b * 1024 + t)) * 64;
                    int base = 16 * rb + 2 * cb;
                    #pragma unroll
                    for (int e = 0; e < 4; e++) {
                        int r = e >> 1, c = e & 1;
                        int mi = base + 8 * r + c;
                        float bv = Mr[mi];
                        Or[mi] = bv + (z4[(i * 4 + e) * 4 + j] - bv) * sg;
                    }
                }
                __syncwarp();
            }
        }
    }
}

// ---------------- launch ----------------
extern "C" void kernel_launch(void* const* d_in, const int* in_sizes, int n_in,
                              void* d_out, int out_size)
{
    const float* M        = (const float*)d_in[0];
    const int*   tok      = (const int*)d_in[1];
    const float* Wqkv_blk = (const float*)d_in[2];
    const float* bqkv_blk = (const float*)d_in[3];
    const float* Wo_blk   = (const float*)d_in[4];
    const float* bo_blk   = (const float*)d_in[5];
    const float* Wqkv_c   = (const float*)d_in[6];
    const float* bqkv_c   = (const float*)d_in[7];
    const float* Wo_c     = (const float*)d_in[8];
    const float* bo_c     = (const float*)d_in[9];
    const float* W1       = (const float*)d_in[10];
    const float* b1       = (const float*)d_in[11];
    const float* W2       = (const float*)d_in[12];
    const float* b2       = (const float*)d_in[13];
    const float* g1       = (const float*)d_in[14];
    const float* be1      = (const float*)d_in[15];
    const float* g2       = (const float*)d_in[16];
    const float* be2      = (const float*)d_in[17];
    const float* semb     = (const float*)d_in[18];
    const float* alpha    = (const float*)d_in[19];
    float* out = (float*)d_out;

    static bool init_done = false;
    if (!init_done) {
        cudaFuncSetAttribute(k_all, cudaFuncAttributeMaxDynamicSharedMemorySize, SMEM_BYTES);
        init_done = true;
    }

    k_all<<<GRID, NTHR, SMEM_BYTES>>>(M, tok, Wqkv_blk, bqkv_blk, Wo_blk, bo_blk,
                                      Wqkv_c, bqkv_c, Wo_c, bo_c, W1, b1, W2, b2,
                                      g1, be1, g2, be2, semb, alpha, out);
}